// round 3
// baseline (speedup 1.0000x reference)
#include <cuda_runtime.h>
#include <math.h>

// Problem constants: B=2, L=8192, D=1024, H=8, d=128
#define NTOK 16384            // B*L
#define DIM  1024
#define NH   8
#define HD   128

// ---------------- scratch (device globals; no allocs allowed) ----------------
__device__ float g_q   [(size_t)NTOK * DIM];      // 64 MB
__device__ float g_feat[(size_t)NTOK * DIM];      // 64 MB
__device__ float g_KV  [16 * HD * HD];            // 1 MB  (B*H matrices of 128x128)
__device__ float g_Ksum[16 * HD];                 // 8 KB
__device__ float g_Z   [(size_t)NTOK * NH];       // 512 KB
__device__ float g_msg [(size_t)NTOK * DIM];      // 64 MB
__device__ float g_msgW[(size_t)NTOK * DIM];      // 64 MB
__device__ float g_x1  [(size_t)NTOK * DIM];      // 64 MB
__device__ float g_hid [(size_t)NTOK * 2 * DIM];  // 128 MB
__device__ float g_mlp [(size_t)NTOK * DIM];      // 64 MB

__global__ void zero_kernel(float* __restrict__ p, int n) {
    int i = blockIdx.x * blockDim.x + threadIdx.x;
    if (i < n) p[i] = 0.f;
}

// ---------------- generic 128x128x16 double-buffered SGEMM -------------------
// EPI: 0 = plain store, 1 = relu, 2 = store C=q and C2=elu(q)+1, 3 = row-scale by Z
// EPI==3 is batched over blockIdx.z = b*8 + h (attention msg = feat @ KV).
template <int EPI>
__global__ void __launch_bounds__(256, 2)
sgemm_k(const float* __restrict__ A, int lda,
        const float* __restrict__ Bm, int ldb,
        float* __restrict__ C, int ldc,
        float* __restrict__ C2,
        const float* __restrict__ Zp,
        int K)
{
    __shared__ float As[2][16][128];
    __shared__ float Bs[2][16][128];

    if (EPI == 3) {
        const int b = blockIdx.z >> 3;
        const int h = blockIdx.z & 7;
        const size_t toff = (size_t)b * 8192 * 1024 + (size_t)h * 128;
        A  += toff;
        C  += toff;
        Bm += (size_t)blockIdx.z * (128 * 128);
        Zp += (size_t)b * 8192 * 8 + h;
    }

    const int tid = threadIdx.x;
    const int ty = tid >> 4;
    const int tx = tid & 15;
    const int m0 = blockIdx.y * 128;
    const int n0 = blockIdx.x * 128;

    // A loader: tile 128(M) x 16(K); two float4 per thread, stored transposed.
    const int arow = tid >> 2;
    const int acol = (tid & 3) << 2;
    // B loader: tile 16(K) x 128(N); two float4 per thread.
    const int brow = tid >> 5;
    const int bcol = (tid & 31) << 2;

    const float* Ap = A  + (size_t)(m0 + arow) * lda + acol;
    const float* Bp = Bm + (size_t)brow * ldb + (n0 + bcol);

    float acc[8][8];
#pragma unroll
    for (int i = 0; i < 8; i++)
#pragma unroll
        for (int j = 0; j < 8; j++) acc[i][j] = 0.f;

    const int nk = K >> 4;

    // prologue: tile 0 -> buffer 0
    {
        float4 a0 = *(const float4*)(Ap);
        float4 a1 = *(const float4*)(Ap + (size_t)64 * lda);
        float4 b0 = *(const float4*)(Bp);
        float4 b1 = *(const float4*)(Bp + (size_t)8 * ldb);
        As[0][acol + 0][arow]      = a0.x;
        As[0][acol + 1][arow]      = a0.y;
        As[0][acol + 2][arow]      = a0.z;
        As[0][acol + 3][arow]      = a0.w;
        As[0][acol + 0][arow + 64] = a1.x;
        As[0][acol + 1][arow + 64] = a1.y;
        As[0][acol + 2][arow + 64] = a1.z;
        As[0][acol + 3][arow + 64] = a1.w;
        *(float4*)&Bs[0][brow][bcol]     = b0;
        *(float4*)&Bs[0][brow + 8][bcol] = b1;
    }
    __syncthreads();

    int cur = 0;
    for (int kt = 0; kt < nk; kt++) {
        float4 a0, a1, b0, b1;
        const bool has = (kt + 1 < nk);
        if (has) {
            const float* Apn = Ap + (kt + 1) * 16;
            const float* Bpn = Bp + (size_t)(kt + 1) * 16 * ldb;
            a0 = *(const float4*)(Apn);
            a1 = *(const float4*)(Apn + (size_t)64 * lda);
            b0 = *(const float4*)(Bpn);
            b1 = *(const float4*)(Bpn + (size_t)8 * ldb);
        }
#pragma unroll
        for (int k = 0; k < 16; k++) {
            float av[8], bv[8];
            *(float4*)&av[0] = *(const float4*)&As[cur][k][ty * 8];
            *(float4*)&av[4] = *(const float4*)&As[cur][k][ty * 8 + 4];
            *(float4*)&bv[0] = *(const float4*)&Bs[cur][k][tx * 8];
            *(float4*)&bv[4] = *(const float4*)&Bs[cur][k][tx * 8 + 4];
#pragma unroll
            for (int i = 0; i < 8; i++)
#pragma unroll
                for (int j = 0; j < 8; j++)
                    acc[i][j] = fmaf(av[i], bv[j], acc[i][j]);
        }
        if (has) {
            const int nb = cur ^ 1;
            As[nb][acol + 0][arow]      = a0.x;
            As[nb][acol + 1][arow]      = a0.y;
            As[nb][acol + 2][arow]      = a0.z;
            As[nb][acol + 3][arow]      = a0.w;
            As[nb][acol + 0][arow + 64] = a1.x;
            As[nb][acol + 1][arow + 64] = a1.y;
            As[nb][acol + 2][arow + 64] = a1.z;
            As[nb][acol + 3][arow + 64] = a1.w;
            *(float4*)&Bs[nb][brow][bcol]     = b0;
            *(float4*)&Bs[nb][brow + 8][bcol] = b1;
            __syncthreads();
            cur = nb;
        }
    }

    // epilogue
#pragma unroll
    for (int i = 0; i < 8; i++) {
        const int r = m0 + ty * 8 + i;
        float zs = 0.f;
        if (EPI == 3) zs = Zp[(size_t)r * 8];
#pragma unroll
        for (int j = 0; j < 8; j += 4) {
            const int c = n0 + tx * 8 + j;
            float4 v = make_float4(acc[i][j], acc[i][j + 1], acc[i][j + 2], acc[i][j + 3]);
            if (EPI == 1) {
                v.x = fmaxf(v.x, 0.f); v.y = fmaxf(v.y, 0.f);
                v.z = fmaxf(v.z, 0.f); v.w = fmaxf(v.w, 0.f);
            }
            if (EPI == 3) { v.x *= zs; v.y *= zs; v.z *= zs; v.w *= zs; }
            *(float4*)(C + (size_t)r * ldc + c) = v;
            if (EPI == 2) {
                // feat = elu(q) + 1  ( = q+1 for q>0, exp(q) otherwise )
                float4 f;
                f.x = v.x > 0.f ? v.x + 1.f : expf(v.x);
                f.y = v.y > 0.f ? v.y + 1.f : expf(v.y);
                f.z = v.z > 0.f ? v.z + 1.f : expf(v.z);
                f.w = v.w > 0.f ? v.w + 1.f : expf(v.w);
                *(float4*)(C2 + (size_t)r * ldc + c) = f;
            }
        }
    }
}

// ---------------- KV = sum_s K[s] (x) V[s]  and  Ksum = sum_s K[s] -----------
// grid: (32 seq slices, 16 bh); each block: 256 seq positions, 128x128 outer
// product accumulated in registers (8x8 per thread), atomicAdd at the end.
__global__ void __launch_bounds__(256)
kv_kernel(const float* __restrict__ feat, const float* __restrict__ q,
          float* __restrict__ KV, float* __restrict__ Ksum)
{
    const int bh = blockIdx.y;
    const int b = bh >> 3, h = bh & 7;
    const float* Kp = feat + (size_t)b * 8192 * 1024 + (size_t)h * 128;
    const float* Vp = q    + (size_t)b * 8192 * 1024 + (size_t)h * 128;
    const int s0 = blockIdx.x * 256;

    __shared__ float Ks[4][128];
    __shared__ float Vs[4][128];

    const int tid = threadIdx.x;
    const int ty = tid >> 4, tx = tid & 15;
    const int lrow = (tid & 127) >> 5;
    const int lcol = ((tid & 127) & 31) << 2;
    const bool loadV = (tid >= 128);

    float acc[8][8];
#pragma unroll
    for (int i = 0; i < 8; i++)
#pragma unroll
        for (int j = 0; j < 8; j++) acc[i][j] = 0.f;
    float ksacc = 0.f;

    for (int s = s0; s < s0 + 256; s += 4) {
        const float* src = loadV ? Vp : Kp;
        float4 v = *(const float4*)(src + (size_t)(s + lrow) * 1024 + lcol);
        float* dst = loadV ? &Vs[lrow][lcol] : &Ks[lrow][lcol];
        *(float4*)dst = v;
        __syncthreads();
#pragma unroll
        for (int ss = 0; ss < 4; ss++) {
            float av[8], bv[8];
            *(float4*)&av[0] = *(const float4*)&Ks[ss][ty * 8];
            *(float4*)&av[4] = *(const float4*)&Ks[ss][ty * 8 + 4];
            *(float4*)&bv[0] = *(const float4*)&Vs[ss][tx * 8];
            *(float4*)&bv[4] = *(const float4*)&Vs[ss][tx * 8 + 4];
#pragma unroll
            for (int i = 0; i < 8; i++)
#pragma unroll
                for (int j = 0; j < 8; j++)
                    acc[i][j] = fmaf(av[i], bv[j], acc[i][j]);
            if (tid < 128) ksacc += Ks[ss][tid];
        }
        __syncthreads();
    }

    float* KVp = KV + (size_t)bh * 128 * 128;
#pragma unroll
    for (int i = 0; i < 8; i++)
#pragma unroll
        for (int j = 0; j < 8; j++)
            atomicAdd(&KVp[(ty * 8 + i) * 128 + tx * 8 + j], acc[i][j]);
    if (tid < 128) atomicAdd(&Ksum[bh * 128 + tid], ksacc);
}

// ---------------- Z = 1 / (Q . Ksum + eps), one warp per (token, head) -------
__global__ void __launch_bounds__(256)
z_kernel(const float* __restrict__ feat, const float* __restrict__ Ksum,
         float* __restrict__ Z)
{
    const int wid  = (blockIdx.x * blockDim.x + threadIdx.x) >> 5;
    const int lane = threadIdx.x & 31;
    const int tok = wid >> 3;
    const int h = wid & 7;
    const int b = tok >> 13;
    float4 f  = *(const float4*)(feat + (size_t)tok * 1024 + h * 128 + lane * 4);
    float4 ks = *(const float4*)(Ksum + ((b * 8 + h) * 128) + lane * 4);
    float s = f.x * ks.x + f.y * ks.y + f.z * ks.z + f.w * ks.w;
#pragma unroll
    for (int o = 16; o; o >>= 1) s += __shfl_xor_sync(0xffffffffu, s, o);
    if (lane == 0) Z[wid] = 1.f / (s + 1e-6f);
}

// ---------------- out = xin + LayerNorm(y; g, beta); one block per row -------
__global__ void __launch_bounds__(256)
ln_kernel(const float* __restrict__ y, const float* __restrict__ xin,
          const float* __restrict__ g, const float* __restrict__ beta,
          float* __restrict__ out)
{
    const int r = blockIdx.x;
    const int tid = threadIdx.x;
    const size_t base = (size_t)r * 1024 + tid * 4;
    float4 v = *(const float4*)(y + base);
    float s  = v.x + v.y + v.z + v.w;
    float sq = v.x * v.x + v.y * v.y + v.z * v.z + v.w * v.w;
#pragma unroll
    for (int o = 16; o; o >>= 1) {
        s  += __shfl_xor_sync(0xffffffffu, s, o);
        sq += __shfl_xor_sync(0xffffffffu, sq, o);
    }
    __shared__ float shs[8], shq[8];
    if ((tid & 31) == 0) { shs[tid >> 5] = s; shq[tid >> 5] = sq; }
    __syncthreads();
    float tot = 0.f, totq = 0.f;
#pragma unroll
    for (int w = 0; w < 8; w++) { tot += shs[w]; totq += shq[w]; }
    const float mu   = tot * (1.f / 1024.f);
    const float var  = totq * (1.f / 1024.f) - mu * mu;
    const float rstd = rsqrtf(var + 1e-5f);
    float4 gv = *(const float4*)(g + tid * 4);
    float4 bv = *(const float4*)(beta + tid * 4);
    float4 xv = *(const float4*)(xin + base);
    float4 o;
    o.x = xv.x + (v.x - mu) * rstd * gv.x + bv.x;
    o.y = xv.y + (v.y - mu) * rstd * gv.y + bv.y;
    o.z = xv.z + (v.z - mu) * rstd * gv.z + bv.z;
    o.w = xv.w + (v.w - mu) * rstd * gv.w + bv.w;
    *(float4*)(out + base) = o;
}

// -----------------------------------------------------------------------------
extern "C" void kernel_launch(void* const* d_in, const int* in_sizes, int n_in,
                              void* d_out, int out_size)
{
    const float* x  = (const float*)d_in[0];
    const float* Wq = (const float*)d_in[1];
    const float* Wm = (const float*)d_in[2];
    const float* W1 = (const float*)d_in[3];
    const float* W2 = (const float*)d_in[4];
    const float* g1 = (const float*)d_in[5];
    const float* b1 = (const float*)d_in[6];
    const float* g2 = (const float*)d_in[7];
    const float* b2 = (const float*)d_in[8];
    float* outp = (float*)d_out;

    float *qp, *featp, *KVp, *Ksump, *Zp, *msgp, *msgWp, *x1p, *hidp, *mlpp;
    cudaGetSymbolAddress((void**)&qp,    g_q);
    cudaGetSymbolAddress((void**)&featp, g_feat);
    cudaGetSymbolAddress((void**)&KVp,   g_KV);
    cudaGetSymbolAddress((void**)&Ksump, g_Ksum);
    cudaGetSymbolAddress((void**)&Zp,    g_Z);
    cudaGetSymbolAddress((void**)&msgp,  g_msg);
    cudaGetSymbolAddress((void**)&msgWp, g_msgW);
    cudaGetSymbolAddress((void**)&x1p,   g_x1);
    cudaGetSymbolAddress((void**)&hidp,  g_hid);
    cudaGetSymbolAddress((void**)&mlpp,  g_mlp);

    const dim3 blk(256);

    // 1) q = x @ Wq ; feat = elu(q)+1   [16384,1024]x[1024,1024]
    sgemm_k<2><<<dim3(8, 128, 1), blk>>>(x, 1024, Wq, 1024, qp, 1024, featp, nullptr, 1024);

    // 2) KV, Ksum accumulation (zero first; atomicAdd accumulate)
    zero_kernel<<<(16 * 128 * 128 + 255) / 256, blk>>>(KVp, 16 * 128 * 128);
    zero_kernel<<<(16 * 128 + 255) / 256, blk>>>(Ksump, 16 * 128);
    kv_kernel<<<dim3(32, 16), blk>>>(featp, qp, KVp, Ksump);

    // 3) Z normalizer
    z_kernel<<<16384, blk>>>(featp, Ksump, Zp);

    // 4) msg = (feat @ KV) * Z   (V=q fold: /L and *L cancel), batched over 16 bh
    sgemm_k<3><<<dim3(1, 64, 16), blk>>>(featp, 1024, KVp, 128, msgp, 1024, nullptr, Zp, 128);

    // 5) msgW = msg @ Wm
    sgemm_k<0><<<dim3(8, 128, 1), blk>>>(msgp, 1024, Wm, 1024, msgWp, 1024, nullptr, nullptr, 1024);

    // 6) x1 = x + LN(msgW; g1, b1)
    ln_kernel<<<16384, blk>>>(msgWp, x, g1, b1, x1p);

    // 7) hid = relu(msgW @ W1)   [16384,1024]x[1024,2048]
    sgemm_k<1><<<dim3(16, 128, 1), blk>>>(msgWp, 1024, W1, 2048, hidp, 2048, nullptr, nullptr, 1024);

    // 8) mlp = hid @ W2          [16384,2048]x[2048,1024]
    sgemm_k<0><<<dim3(8, 128, 1), blk>>>(hidp, 2048, W2, 1024, mlpp, 1024, nullptr, nullptr, 2048);

    // 9) out = x1 + LN(mlp; g2, b2)
    ln_kernel<<<16384, blk>>>(mlpp, x1p, g2, b2, outp);
}

// round 10
// speedup vs baseline: 2.4733x; 2.4733x over previous
#include <cuda_runtime.h>
#include <cuda_bf16.h>
#include <math.h>
#include <stdint.h>

// Problem constants: B=2, L=8192, D=1024, H=8, d=128
#define NTOK 16384            // B*L
#define DIM  1024
#define NH   8
#define HD   128

// ---------------- scratch (device globals; no allocs allowed) ----------------
__device__ float g_q   [(size_t)NTOK * DIM];
__device__ float g_feat[(size_t)NTOK * DIM];
__device__ float g_KV  [16 * HD * HD];
__device__ float g_Ksum[16 * HD];
__device__ float g_Z   [(size_t)NTOK * NH];
__device__ float g_msg [(size_t)NTOK * DIM];
__device__ float g_msgW[(size_t)NTOK * DIM];
__device__ float g_x1  [(size_t)NTOK * DIM];
__device__ float g_mlp [(size_t)NTOK * DIM];

// bf16 split operands
__device__ __nv_bfloat16 g_xhi [(size_t)NTOK * DIM];
__device__ __nv_bfloat16 g_xlo [(size_t)NTOK * DIM];
__device__ __nv_bfloat16 g_msghi[(size_t)NTOK * DIM];
__device__ __nv_bfloat16 g_msglo[(size_t)NTOK * DIM];
__device__ __nv_bfloat16 g_mwhi[(size_t)NTOK * DIM];
__device__ __nv_bfloat16 g_mwlo[(size_t)NTOK * DIM];
__device__ __nv_bfloat16 g_hidhi[(size_t)NTOK * 2 * DIM];
__device__ __nv_bfloat16 g_hidlo[(size_t)NTOK * 2 * DIM];
__device__ __nv_bfloat16 g_wqt_h[DIM * DIM];
__device__ __nv_bfloat16 g_wqt_l[DIM * DIM];
__device__ __nv_bfloat16 g_wmt_h[DIM * DIM];
__device__ __nv_bfloat16 g_wmt_l[DIM * DIM];
__device__ __nv_bfloat16 g_w1t_h[2 * DIM * DIM];
__device__ __nv_bfloat16 g_w1t_l[2 * DIM * DIM];
__device__ __nv_bfloat16 g_w2t_h[2 * DIM * DIM];
__device__ __nv_bfloat16 g_w2t_l[2 * DIM * DIM];

// =========================== helpers =========================================
__device__ __forceinline__ uint32_t smem_to_u32(const void* p) {
    uint32_t a;
    asm("{ .reg .u64 t; cvta.to.shared.u64 t, %1; cvt.u32.u64 %0, t; }"
        : "=r"(a) : "l"(p));
    return a;
}

#define SMEM_SWIZZLE_128B(o) ((o) ^ (((o) >> 3) & 0x70))

#define CP_ASYNC16(smem_u32, gptr) \
    asm volatile("cp.async.cg.shared.global [%0], [%1], 16;" \
        :: "r"(smem_u32), "l"(gptr))
#define CP_COMMIT() asm volatile("cp.async.commit_group;" ::: "memory")
#define CP_WAIT2()  asm volatile("cp.async.wait_group 2;" ::: "memory")

#define LDSM4(r0, r1, r2, r3, addr) \
    asm volatile("ldmatrix.sync.aligned.m8n8.x4.shared.b16 {%0,%1,%2,%3}, [%4];" \
        : "=r"(r0), "=r"(r1), "=r"(r2), "=r"(r3) : "r"(addr))

__device__ __forceinline__ void mma16816(float* c, const uint32_t* a,
                                         uint32_t b0, uint32_t b1) {
    asm volatile(
        "mma.sync.aligned.m16n8k16.row.col.f32.bf16.bf16.f32 "
        "{%0,%1,%2,%3}, {%4,%5,%6,%7}, {%8,%9}, {%0,%1,%2,%3};"
        : "+f"(c[0]), "+f"(c[1]), "+f"(c[2]), "+f"(c[3])
        : "r"(a[0]), "r"(a[1]), "r"(a[2]), "r"(a[3]), "r"(b0), "r"(b1));
}

// SMEM: 3 stages x (Ahi,Alo,Bhi,Blo tiles of 128x64 bf16 = 16KB each) = 192KB
static constexpr int MG_STAGE = 65536;
static constexpr int MG_SMEM  = 3 * MG_STAGE;   // 196608

// =============== mma.sync split-bf16 GEMM: C[M,N] = A[M,K] @ B^T =============
// A: [M,K] K-major (hi/lo bf16).  B: [N,K] K-major (hi/lo bf16, i.e. W^T).
// EPI 0: store C fp32.  EPI 1: store C=q fp32 and C2=elu(q)+1 fp32.
// EPI 2: relu, store Chi/Clo bf16 split (no fp32).
__device__ __forceinline__ void mg_load_stage(
    uint32_t sdst,
    const __nv_bfloat16* __restrict__ Ahi, const __nv_bfloat16* __restrict__ Alo,
    const __nv_bfloat16* __restrict__ Bhi, const __nv_bfloat16* __restrict__ Blo,
    int m0, int n0, int K, int kk, int tid)
{
#pragma unroll
    for (int j = 0; j < 4; j++) {
        const int c = tid + j * 256;
        const int row = c >> 3;
        const int k8 = (c & 7) * 8;
        const size_t ga = (size_t)(m0 + row) * K + kk + k8;
        const size_t gb = (size_t)(n0 + row) * K + kk + k8;
        const uint32_t so = SMEM_SWIZZLE_128B((uint32_t)(row * 128 + k8 * 2));
        CP_ASYNC16(sdst + so,         Ahi + ga);
        CP_ASYNC16(sdst + 16384 + so, Alo + ga);
        CP_ASYNC16(sdst + 32768 + so, Bhi + gb);
        CP_ASYNC16(sdst + 49152 + so, Blo + gb);
    }
}

template <int EPI>
__global__ void __launch_bounds__(256, 1)
mma_gemm(const __nv_bfloat16* __restrict__ Ahi, const __nv_bfloat16* __restrict__ Alo,
         const __nv_bfloat16* __restrict__ Bhi, const __nv_bfloat16* __restrict__ Blo,
         float* __restrict__ C, float* __restrict__ C2,
         __nv_bfloat16* __restrict__ Chi, __nv_bfloat16* __restrict__ Clo,
         int K, int N)
{
    extern __shared__ char smem[];
    const uint32_t sb = smem_to_u32(smem);
    const int tid  = threadIdx.x;
    const int lane = tid & 31;
    const int wid  = tid >> 5;
    const int wm   = wid & 1;     // 2 M-groups of 64 rows
    const int wn   = wid >> 1;    // 4 N-groups of 32 cols
    const int m0 = blockIdx.y * 128;
    const int n0 = blockIdx.x * 128;
    const int nk = K >> 6;

    float acc[4][4][4];
#pragma unroll
    for (int i = 0; i < 4; i++)
#pragma unroll
        for (int j = 0; j < 4; j++)
#pragma unroll
            for (int p = 0; p < 4; p++) acc[i][j][p] = 0.f;

    // prologue: fill 3 stages
#pragma unroll
    for (int s = 0; s < 3; s++) {
        if (s < nk) mg_load_stage(sb + s * MG_STAGE, Ahi, Alo, Bhi, Blo,
                                  m0, n0, K, s * 64, tid);
        CP_COMMIT();
    }

    // A-frag ldmatrix address pieces (within a stage/tile)
    const int a_row  = (lane & 15);         // + wm*64 + mt*16
    const int a_colh = (lane >> 4) * 16;    // k-half byte offset
    // B-frag pieces
    const int b_row  = ((lane >> 4) << 3) + (lane & 7);  // + wn*32 + lg*16
    const int b_colh = ((lane >> 3) & 1) * 16;

    for (int kt = 0; kt < nk; kt++) {
        CP_WAIT2();
        __syncthreads();
        const uint32_t sa = sb + (kt % 3) * MG_STAGE;

#pragma unroll
        for (int ks = 0; ks < 4; ks++) {
            const int kb = ks * 32;
            uint32_t ah[4][4], al[4][4];
#pragma unroll
            for (int mt = 0; mt < 4; mt++) {
                const int row = wm * 64 + mt * 16 + a_row;
                const uint32_t off = SMEM_SWIZZLE_128B((uint32_t)(row * 128 + kb + a_colh));
                LDSM4(ah[mt][0], ah[mt][1], ah[mt][2], ah[mt][3], sa + off);
                LDSM4(al[mt][0], al[mt][1], al[mt][2], al[mt][3], sa + 16384 + off);
            }
            uint32_t bh[4][2], bl[4][2];
#pragma unroll
            for (int lg = 0; lg < 2; lg++) {
                const int row = wn * 32 + lg * 16 + b_row;
                const uint32_t off = SMEM_SWIZZLE_128B((uint32_t)(row * 128 + kb + b_colh));
                uint32_t r0, r1, r2, r3;
                LDSM4(r0, r1, r2, r3, sa + 32768 + off);
                bh[lg * 2][0] = r0; bh[lg * 2][1] = r1;
                bh[lg * 2 + 1][0] = r2; bh[lg * 2 + 1][1] = r3;
                LDSM4(r0, r1, r2, r3, sa + 49152 + off);
                bl[lg * 2][0] = r0; bl[lg * 2][1] = r1;
                bl[lg * 2 + 1][0] = r2; bl[lg * 2 + 1][1] = r3;
            }
#pragma unroll
            for (int mt = 0; mt < 4; mt++)
#pragma unroll
                for (int nf = 0; nf < 4; nf++) {
                    mma16816(acc[mt][nf], ah[mt], bh[nf][0], bh[nf][1]);
                    mma16816(acc[mt][nf], ah[mt], bl[nf][0], bl[nf][1]);
                    mma16816(acc[mt][nf], al[mt], bh[nf][0], bh[nf][1]);
                }
        }
        __syncthreads();
        if (kt + 3 < nk)
            mg_load_stage(sb + (kt % 3) * MG_STAGE, Ahi, Alo, Bhi, Blo,
                          m0, n0, K, (kt + 3) * 64, tid);
        CP_COMMIT();
    }

    // -------- epilogue: acc -> gmem --------
#pragma unroll
    for (int mt = 0; mt < 4; mt++) {
#pragma unroll
        for (int nf = 0; nf < 4; nf++) {
            const int r0 = m0 + wm * 64 + mt * 16 + (lane >> 2);
            const int c0 = n0 + wn * 32 + nf * 8 + (lane & 3) * 2;
#pragma unroll
            for (int half = 0; half < 2; half++) {
                const int r = r0 + half * 8;
                float vx = acc[mt][nf][half * 2];
                float vy = acc[mt][nf][half * 2 + 1];
                const size_t o = (size_t)r * N + c0;
                if (EPI == 2) {
                    vx = fmaxf(vx, 0.f);
                    vy = fmaxf(vy, 0.f);
                    __nv_bfloat162 hh, ll;
                    hh.x = __float2bfloat16_rn(vx);
                    hh.y = __float2bfloat16_rn(vy);
                    ll.x = __float2bfloat16_rn(vx - __bfloat162float(hh.x));
                    ll.y = __float2bfloat16_rn(vy - __bfloat162float(hh.y));
                    *(__nv_bfloat162*)(Chi + o) = hh;
                    *(__nv_bfloat162*)(Clo + o) = ll;
                } else {
                    *(float2*)(C + o) = make_float2(vx, vy);
                    if (EPI == 1) {
                        float2 f;
                        f.x = vx > 0.f ? vx + 1.f : expf(vx);
                        f.y = vy > 0.f ? vy + 1.f : expf(vy);
                        *(float2*)(C2 + o) = f;
                    }
                }
            }
        }
    }
}

// ===================== fp32 -> bf16 hi/lo split (vectorized) =================
__device__ __forceinline__ void split1(float a, __nv_bfloat16& h, __nv_bfloat16& l) {
    h = __float2bfloat16_rn(a);
    l = __float2bfloat16_rn(a - __bfloat162float(h));
}
__global__ void cvt_hilo(const float4* __restrict__ in, uint2* __restrict__ hi,
                         uint2* __restrict__ lo, int n4)
{
    int i = blockIdx.x * blockDim.x + threadIdx.x;
    if (i >= n4) return;
    float4 v = in[i];
    __nv_bfloat162 h01, h23, l01, l23;
    split1(v.x, h01.x, l01.x); split1(v.y, h01.y, l01.y);
    split1(v.z, h23.x, l23.x); split1(v.w, h23.y, l23.y);
    hi[i] = make_uint2(*reinterpret_cast<uint32_t*>(&h01), *reinterpret_cast<uint32_t*>(&h23));
    lo[i] = make_uint2(*reinterpret_cast<uint32_t*>(&l01), *reinterpret_cast<uint32_t*>(&l23));
}

// =============== weight transpose + split: W[K,N] -> WT hi/lo [N,K] ==========
__global__ void wtrans(const float* __restrict__ W, __nv_bfloat16* __restrict__ hi,
                       __nv_bfloat16* __restrict__ lo, int K, int N)
{
    __shared__ float t[32][33];
    const int n0 = blockIdx.x * 32, k0 = blockIdx.y * 32;
    const int tx = threadIdx.x, ty = threadIdx.y;
#pragma unroll
    for (int r = 0; r < 4; r++)
        t[ty + 8 * r][tx] = W[(size_t)(k0 + ty + 8 * r) * N + n0 + tx];
    __syncthreads();
#pragma unroll
    for (int r = 0; r < 4; r++) {
        float v = t[tx][ty + 8 * r];
        __nv_bfloat16 h, l;
        split1(v, h, l);
        const size_t o = (size_t)(n0 + ty + 8 * r) * K + k0 + tx;
        hi[o] = h; lo[o] = l;
    }
}

__global__ void zero_kernel(float* __restrict__ p, int n) {
    int i = blockIdx.x * blockDim.x + threadIdx.x;
    if (i < n) p[i] = 0.f;
}

// ---------------- FFMA SGEMM kept only for msg = (feat @ KV) * Z -------------
template <int EPI>
__global__ void __launch_bounds__(256, 2)
sgemm_k(const float* __restrict__ A, int lda,
        const float* __restrict__ Bm, int ldb,
        float* __restrict__ C, int ldc,
        float* __restrict__ C2,
        const float* __restrict__ Zp,
        int K)
{
    __shared__ float As[2][16][128];
    __shared__ float Bs[2][16][128];

    if (EPI == 3) {
        const int b = blockIdx.z >> 3;
        const int h = blockIdx.z & 7;
        const size_t toff = (size_t)b * 8192 * 1024 + (size_t)h * 128;
        A  += toff;
        C  += toff;
        Bm += (size_t)blockIdx.z * (128 * 128);
        Zp += (size_t)b * 8192 * 8 + h;
    }

    const int tid = threadIdx.x;
    const int ty = tid >> 4;
    const int tx = tid & 15;
    const int m0 = blockIdx.y * 128;
    const int n0 = blockIdx.x * 128;

    const int arow = tid >> 2;
    const int acol = (tid & 3) << 2;
    const int brow = tid >> 5;
    const int bcol = (tid & 31) << 2;

    const float* Ap = A  + (size_t)(m0 + arow) * lda + acol;
    const float* Bp = Bm + (size_t)brow * ldb + (n0 + bcol);

    float acc[8][8];
#pragma unroll
    for (int i = 0; i < 8; i++)
#pragma unroll
        for (int j = 0; j < 8; j++) acc[i][j] = 0.f;

    const int nk = K >> 4;
    {
        float4 a0 = *(const float4*)(Ap);
        float4 a1 = *(const float4*)(Ap + (size_t)64 * lda);
        float4 b0 = *(const float4*)(Bp);
        float4 b1 = *(const float4*)(Bp + (size_t)8 * ldb);
        As[0][acol + 0][arow]      = a0.x; As[0][acol + 1][arow]      = a0.y;
        As[0][acol + 2][arow]      = a0.z; As[0][acol + 3][arow]      = a0.w;
        As[0][acol + 0][arow + 64] = a1.x; As[0][acol + 1][arow + 64] = a1.y;
        As[0][acol + 2][arow + 64] = a1.z; As[0][acol + 3][arow + 64] = a1.w;
        *(float4*)&Bs[0][brow][bcol]     = b0;
        *(float4*)&Bs[0][brow + 8][bcol] = b1;
    }
    __syncthreads();

    int cur = 0;
    for (int kt = 0; kt < nk; kt++) {
        float4 a0, a1, b0, b1;
        const bool has = (kt + 1 < nk);
        if (has) {
            const float* Apn = Ap + (kt + 1) * 16;
            const float* Bpn = Bp + (size_t)(kt + 1) * 16 * ldb;
            a0 = *(const float4*)(Apn);
            a1 = *(const float4*)(Apn + (size_t)64 * lda);
            b0 = *(const float4*)(Bpn);
            b1 = *(const float4*)(Bpn + (size_t)8 * ldb);
        }
#pragma unroll
        for (int k = 0; k < 16; k++) {
            float av[8], bv[8];
            *(float4*)&av[0] = *(const float4*)&As[cur][k][ty * 8];
            *(float4*)&av[4] = *(const float4*)&As[cur][k][ty * 8 + 4];
            *(float4*)&bv[0] = *(const float4*)&Bs[cur][k][tx * 8];
            *(float4*)&bv[4] = *(const float4*)&Bs[cur][k][tx * 8 + 4];
#pragma unroll
            for (int i = 0; i < 8; i++)
#pragma unroll
                for (int j = 0; j < 8; j++)
                    acc[i][j] = fmaf(av[i], bv[j], acc[i][j]);
        }
        if (has) {
            const int nb = cur ^ 1;
            As[nb][acol + 0][arow]      = a0.x; As[nb][acol + 1][arow]      = a0.y;
            As[nb][acol + 2][arow]      = a0.z; As[nb][acol + 3][arow]      = a0.w;
            As[nb][acol + 0][arow + 64] = a1.x; As[nb][acol + 1][arow + 64] = a1.y;
            As[nb][acol + 2][arow + 64] = a1.z; As[nb][acol + 3][arow + 64] = a1.w;
            *(float4*)&Bs[nb][brow][bcol]     = b0;
            *(float4*)&Bs[nb][brow + 8][bcol] = b1;
            __syncthreads();
            cur = nb;
        }
    }
#pragma unroll
    for (int i = 0; i < 8; i++) {
        const int r = m0 + ty * 8 + i;
        float zs = 0.f;
        if (EPI == 3) zs = Zp[(size_t)r * 8];
#pragma unroll
        for (int j = 0; j < 8; j += 4) {
            const int c = n0 + tx * 8 + j;
            float4 v = make_float4(acc[i][j], acc[i][j + 1], acc[i][j + 2], acc[i][j + 3]);
            if (EPI == 3) { v.x *= zs; v.y *= zs; v.z *= zs; v.w *= zs; }
            *(float4*)(C + (size_t)r * ldc + c) = v;
        }
    }
}

// ---------------- KV = sum_s K[s] (x) V[s]  and  Ksum = sum_s K[s] -----------
__global__ void __launch_bounds__(256)
kv_kernel(const float* __restrict__ feat, const float* __restrict__ q,
          float* __restrict__ KV, float* __restrict__ Ksum)
{
    const int bh = blockIdx.y;
    const int b = bh >> 3, h = bh & 7;
    const float* Kp = feat + (size_t)b * 8192 * 1024 + (size_t)h * 128;
    const float* Vp = q    + (size_t)b * 8192 * 1024 + (size_t)h * 128;
    const int s0 = blockIdx.x * 256;

    __shared__ float Ks[4][128];
    __shared__ float Vs[4][128];

    const int tid = threadIdx.x;
    const int ty = tid >> 4, tx = tid & 15;
    const int lrow = (tid & 127) >> 5;
    const int lcol = ((tid & 127) & 31) << 2;
    const bool loadV = (tid >= 128);

    float acc[8][8];
#pragma unroll
    for (int i = 0; i < 8; i++)
#pragma unroll
        for (int j = 0; j < 8; j++) acc[i][j] = 0.f;
    float ksacc = 0.f;

    for (int s = s0; s < s0 + 256; s += 4) {
        const float* src = loadV ? Vp : Kp;
        float4 v = *(const float4*)(src + (size_t)(s + lrow) * 1024 + lcol);
        float* dst = loadV ? &Vs[lrow][lcol] : &Ks[lrow][lcol];
        *(float4*)dst = v;
        __syncthreads();
#pragma unroll
        for (int ss = 0; ss < 4; ss++) {
            float av[8], bv[8];
            *(float4*)&av[0] = *(const float4*)&Ks[ss][ty * 8];
            *(float4*)&av[4] = *(const float4*)&Ks[ss][ty * 8 + 4];
            *(float4*)&bv[0] = *(const float4*)&Vs[ss][tx * 8];
            *(float4*)&bv[4] = *(const float4*)&Vs[ss][tx * 8 + 4];
#pragma unroll
            for (int i = 0; i < 8; i++)
#pragma unroll
                for (int j = 0; j < 8; j++)
                    acc[i][j] = fmaf(av[i], bv[j], acc[i][j]);
            if (tid < 128) ksacc += Ks[ss][tid];
        }
        __syncthreads();
    }

    float* KVp = KV + (size_t)bh * 128 * 128;
#pragma unroll
    for (int i = 0; i < 8; i++)
#pragma unroll
        for (int j = 0; j < 8; j++)
            atomicAdd(&KVp[(ty * 8 + i) * 128 + tx * 8 + j], acc[i][j]);
    if (tid < 128) atomicAdd(&Ksum[bh * 128 + tid], ksacc);
}

// ---------------- Z = 1 / (Q . Ksum + eps) -----------------------------------
__global__ void __launch_bounds__(256)
z_kernel(const float* __restrict__ feat, const float* __restrict__ Ksum,
         float* __restrict__ Z)
{
    const int wid  = (blockIdx.x * blockDim.x + threadIdx.x) >> 5;
    const int lane = threadIdx.x & 31;
    const int tok = wid >> 3;
    const int h = wid & 7;
    const int b = tok >> 13;
    float4 f  = *(const float4*)(feat + (size_t)tok * 1024 + h * 128 + lane * 4);
    float4 ks = *(const float4*)(Ksum + ((b * 8 + h) * 128) + lane * 4);
    float s = f.x * ks.x + f.y * ks.y + f.z * ks.z + f.w * ks.w;
#pragma unroll
    for (int o = 16; o; o >>= 1) s += __shfl_xor_sync(0xffffffffu, s, o);
    if (lane == 0) Z[wid] = 1.f / (s + 1e-6f);
}

// ---------------- out = xin + LayerNorm(y; g, beta) --------------------------
__global__ void __launch_bounds__(256)
ln_kernel(const float* __restrict__ y, const float* __restrict__ xin,
          const float* __restrict__ g, const float* __restrict__ beta,
          float* __restrict__ out)
{
    const int r = blockIdx.x;
    const int tid = threadIdx.x;
    const size_t base = (size_t)r * 1024 + tid * 4;
    float4 v = *(const float4*)(y + base);
    float s  = v.x + v.y + v.z + v.w;
    float sq = v.x * v.x + v.y * v.y + v.z * v.z + v.w * v.w;
#pragma unroll
    for (int o = 16; o; o >>= 1) {
        s  += __shfl_xor_sync(0xffffffffu, s, o);
        sq += __shfl_xor_sync(0xffffffffu, sq, o);
    }
    __shared__ float shs[8], shq[8];
    if ((tid & 31) == 0) { shs[tid >> 5] = s; shq[tid >> 5] = sq; }
    __syncthreads();
    float tot = 0.f, totq = 0.f;
#pragma unroll
    for (int w = 0; w < 8; w++) { tot += shs[w]; totq += shq[w]; }
    const float mu   = tot * (1.f / 1024.f);
    const float var  = totq * (1.f / 1024.f) - mu * mu;
    const float rstd = rsqrtf(var + 1e-5f);
    float4 gv = *(const float4*)(g + tid * 4);
    float4 bv = *(const float4*)(beta + tid * 4);
    float4 xv = *(const float4*)(xin + base);
    float4 o;
    o.x = xv.x + (v.x - mu) * rstd * gv.x + bv.x;
    o.y = xv.y + (v.y - mu) * rstd * gv.y + bv.y;
    o.z = xv.z + (v.z - mu) * rstd * gv.z + bv.z;
    o.w = xv.w + (v.w - mu) * rstd * gv.w + bv.w;
    *(float4*)(out + base) = o;
}

// -----------------------------------------------------------------------------
extern "C" void kernel_launch(void* const* d_in, const int* in_sizes, int n_in,
                              void* d_out, int out_size)
{
    const float* x  = (const float*)d_in[0];
    const float* Wq = (const float*)d_in[1];
    const float* Wm = (const float*)d_in[2];
    const float* W1 = (const float*)d_in[3];
    const float* W2 = (const float*)d_in[4];
    const float* g1 = (const float*)d_in[5];
    const float* b1 = (const float*)d_in[6];
    const float* g2 = (const float*)d_in[7];
    const float* b2 = (const float*)d_in[8];
    float* outp = (float*)d_out;

    float *qp, *featp, *KVp, *Ksump, *Zp, *msgp, *msgWp, *x1p, *mlpp;
    cudaGetSymbolAddress((void**)&qp,    g_q);
    cudaGetSymbolAddress((void**)&featp, g_feat);
    cudaGetSymbolAddress((void**)&KVp,   g_KV);
    cudaGetSymbolAddress((void**)&Ksump, g_Ksum);
    cudaGetSymbolAddress((void**)&Zp,    g_Z);
    cudaGetSymbolAddress((void**)&msgp,  g_msg);
    cudaGetSymbolAddress((void**)&msgWp, g_msgW);
    cudaGetSymbolAddress((void**)&x1p,   g_x1);
    cudaGetSymbolAddress((void**)&mlpp,  g_mlp);

    __nv_bfloat16 *xhi, *xlo, *msghi, *msglo, *mwhi, *mwlo, *hidhi, *hidlo;
    __nv_bfloat16 *wqh, *wql, *wmh, *wml, *w1h, *w1l, *w2h, *w2l;
    cudaGetSymbolAddress((void**)&xhi,   g_xhi);
    cudaGetSymbolAddress((void**)&xlo,   g_xlo);
    cudaGetSymbolAddress((void**)&msghi, g_msghi);
    cudaGetSymbolAddress((void**)&msglo, g_msglo);
    cudaGetSymbolAddress((void**)&mwhi,  g_mwhi);
    cudaGetSymbolAddress((void**)&mwlo,  g_mwlo);
    cudaGetSymbolAddress((void**)&hidhi, g_hidhi);
    cudaGetSymbolAddress((void**)&hidlo, g_hidlo);
    cudaGetSymbolAddress((void**)&wqh,   g_wqt_h);
    cudaGetSymbolAddress((void**)&wql,   g_wqt_l);
    cudaGetSymbolAddress((void**)&wmh,   g_wmt_h);
    cudaGetSymbolAddress((void**)&wml,   g_wmt_l);
    cudaGetSymbolAddress((void**)&w1h,   g_w1t_h);
    cudaGetSymbolAddress((void**)&w1l,   g_w1t_l);
    cudaGetSymbolAddress((void**)&w2h,   g_w2t_h);
    cudaGetSymbolAddress((void**)&w2l,   g_w2t_l);

    cudaFuncSetAttribute(mma_gemm<0>, cudaFuncAttributeMaxDynamicSharedMemorySize, MG_SMEM);
    cudaFuncSetAttribute(mma_gemm<1>, cudaFuncAttributeMaxDynamicSharedMemorySize, MG_SMEM);
    cudaFuncSetAttribute(mma_gemm<2>, cudaFuncAttributeMaxDynamicSharedMemorySize, MG_SMEM);

    const dim3 blk(256);
    const dim3 tblk(32, 8);
    const int n4 = NTOK * DIM / 4;

    // ---- weight transpose + split; x split ----
    wtrans<<<dim3(32, 32), tblk>>>(Wq, wqh, wql, 1024, 1024);
    wtrans<<<dim3(32, 32), tblk>>>(Wm, wmh, wml, 1024, 1024);
    wtrans<<<dim3(64, 32), tblk>>>(W1, w1h, w1l, 1024, 2048);
    wtrans<<<dim3(32, 64), tblk>>>(W2, w2h, w2l, 2048, 1024);
    cvt_hilo<<<n4 / 256, blk>>>((const float4*)x, (uint2*)xhi, (uint2*)xlo, n4);

    // 1) q = x @ Wq ; feat = elu(q)+1   (mma.sync)
    mma_gemm<1><<<dim3(8, 128), blk, MG_SMEM>>>(xhi, xlo, wqh, wql,
                                                qp, featp, nullptr, nullptr, 1024, 1024);

    // 2) KV / Ksum
    zero_kernel<<<(16 * 128 * 128 + 255) / 256, blk>>>(KVp, 16 * 128 * 128);
    zero_kernel<<<(16 * 128 + 255) / 256, blk>>>(Ksump, 16 * 128);
    kv_kernel<<<dim3(32, 16), blk>>>(featp, qp, KVp, Ksump);

    // 3) Z normalizer
    z_kernel<<<16384, blk>>>(featp, Ksump, Zp);

    // 4) msg = (feat @ KV) * Z   (FFMA, K=128 per head)
    sgemm_k<3><<<dim3(1, 64, 16), blk>>>(featp, 1024, KVp, 128, msgp, 1024, nullptr, Zp, 128);

    // 5) msgW = msg @ Wm   (mma.sync)
    cvt_hilo<<<n4 / 256, blk>>>((const float4*)msgp, (uint2*)msghi, (uint2*)msglo, n4);
    mma_gemm<0><<<dim3(8, 128), blk, MG_SMEM>>>(msghi, msglo, wmh, wml,
                                                msgWp, nullptr, nullptr, nullptr, 1024, 1024);

    // 6) x1 = x + LN(msgW)
    ln_kernel<<<16384, blk>>>(msgWp, x, g1, b1, x1p);

    // 7) hid = relu(msgW @ W1), emitted as bf16 hi/lo   (mma.sync)
    cvt_hilo<<<n4 / 256, blk>>>((const float4*)msgWp, (uint2*)mwhi, (uint2*)mwlo, n4);
    mma_gemm<2><<<dim3(16, 128), blk, MG_SMEM>>>(mwhi, mwlo, w1h, w1l,
                                                 nullptr, nullptr, hidhi, hidlo, 1024, 2048);

    // 8) mlp = hid @ W2   (mma.sync, K=2048)
    mma_gemm<0><<<dim3(8, 128), blk, MG_SMEM>>>(hidhi, hidlo, w2h, w2l,
                                                mlpp, nullptr, nullptr, nullptr, 2048, 1024);

    // 9) out = x1 + LN(mlp)
    ln_kernel<<<16384, blk>>>(mlpp, x1p, g2, b2, outp);
}

// round 12
// speedup vs baseline: 2.5541x; 1.0326x over previous
#include <cuda_runtime.h>
#include <cuda_bf16.h>
#include <math.h>
#include <stdint.h>

// Problem constants: B=2, L=8192, D=1024, H=8, d=128
#define NTOK 16384            // B*L
#define DIM  1024
#define NH   8
#define HD   128

// ---------------- scratch (device globals; no allocs allowed) ----------------
__device__ float g_q   [(size_t)NTOK * DIM];
__device__ float g_feat[(size_t)NTOK * DIM];
__device__ float g_KV  [16 * HD * HD];    // holds KV^T per (b,h): [v][d]
__device__ float g_Ksum[16 * HD];
__device__ float g_Z   [(size_t)NTOK * NH];
__device__ float g_msgW[(size_t)NTOK * DIM];
__device__ float g_x1  [(size_t)NTOK * DIM];
__device__ float g_mlp [(size_t)NTOK * DIM];

// bf16 split operands
__device__ __nv_bfloat16 g_xhi  [(size_t)NTOK * DIM];
__device__ __nv_bfloat16 g_xlo  [(size_t)NTOK * DIM];
__device__ __nv_bfloat16 g_fhi  [(size_t)NTOK * DIM];   // feat hi
__device__ __nv_bfloat16 g_flo  [(size_t)NTOK * DIM];   // feat lo
__device__ __nv_bfloat16 g_msghi[(size_t)NTOK * DIM];
__device__ __nv_bfloat16 g_msglo[(size_t)NTOK * DIM];
__device__ __nv_bfloat16 g_mwhi [(size_t)NTOK * DIM];
__device__ __nv_bfloat16 g_mwlo [(size_t)NTOK * DIM];
__device__ __nv_bfloat16 g_hidhi[(size_t)NTOK * 2 * DIM];
__device__ __nv_bfloat16 g_hidlo[(size_t)NTOK * 2 * DIM];
__device__ __nv_bfloat16 g_KVhi [16 * HD * HD];
__device__ __nv_bfloat16 g_KVlo [16 * HD * HD];
__device__ __nv_bfloat16 g_wqt_h[DIM * DIM];
__device__ __nv_bfloat16 g_wqt_l[DIM * DIM];
__device__ __nv_bfloat16 g_wmt_h[DIM * DIM];
__device__ __nv_bfloat16 g_wmt_l[DIM * DIM];
__device__ __nv_bfloat16 g_w1t_h[2 * DIM * DIM];
__device__ __nv_bfloat16 g_w1t_l[2 * DIM * DIM];
__device__ __nv_bfloat16 g_w2t_h[2 * DIM * DIM];
__device__ __nv_bfloat16 g_w2t_l[2 * DIM * DIM];

// =========================== helpers =========================================
__device__ __forceinline__ uint32_t smem_to_u32(const void* p) {
    uint32_t a;
    asm("{ .reg .u64 t; cvta.to.shared.u64 t, %1; cvt.u32.u64 %0, t; }"
        : "=r"(a) : "l"(p));
    return a;
}

#define SMEM_SWIZZLE_128B(o) ((o) ^ (((o) >> 3) & 0x70))

#define CP_ASYNC16(smem_u32, gptr) \
    asm volatile("cp.async.cg.shared.global [%0], [%1], 16;" \
        :: "r"(smem_u32), "l"(gptr))
#define CP_COMMIT() asm volatile("cp.async.commit_group;" ::: "memory")
#define CP_WAIT2()  asm volatile("cp.async.wait_group 2;" ::: "memory")

#define LDSM4(r0, r1, r2, r3, addr) \
    asm volatile("ldmatrix.sync.aligned.m8n8.x4.shared.b16 {%0,%1,%2,%3}, [%4];" \
        : "=r"(r0), "=r"(r1), "=r"(r2), "=r"(r3) : "r"(addr))

__device__ __forceinline__ void mma16816(float* c, const uint32_t* a,
                                         uint32_t b0, uint32_t b1) {
    asm volatile(
        "mma.sync.aligned.m16n8k16.row.col.f32.bf16.bf16.f32 "
        "{%0,%1,%2,%3}, {%4,%5,%6,%7}, {%8,%9}, {%0,%1,%2,%3};"
        : "+f"(c[0]), "+f"(c[1]), "+f"(c[2]), "+f"(c[3])
        : "r"(a[0]), "r"(a[1]), "r"(a[2]), "r"(a[3]), "r"(b0), "r"(b1));
}

__device__ __forceinline__ void split1(float a, __nv_bfloat16& h, __nv_bfloat16& l) {
    h = __float2bfloat16_rn(a);
    l = __float2bfloat16_rn(a - __bfloat162float(h));
}

// SMEM: 3 stages x (Ahi,Alo,Bhi,Blo tiles of 128x64 bf16 = 16KB each) = 192KB
static constexpr int MG_STAGE = 65536;
static constexpr int MG_SMEM  = 3 * MG_STAGE;   // 196608

// =============== mma.sync split-bf16 GEMM: C[M,N] = A[M,K] @ B^T =============
// A: [M,K] rows stride lda (hi/lo bf16).  B: [N,K] rows stride ldb (W^T form).
// EPI 0: store Cf fp32.
// EPI 1: store Cf=q fp32, Cf2=feat fp32, Chi/Clo = feat hi/lo (feat=elu(q)+1).
// EPI 2: relu, store Chi/Clo bf16 split.
// EPI 3: batched over blockIdx.z=bh; scale by Z; store Chi/Clo = msg hi/lo.
//        (B operand must be KV^T in [N=v, K=d] layout)
// EPI 4: store Cf fp32 AND Chi/Clo bf16 split.
__device__ __forceinline__ void mg_load_stage(
    uint32_t sdst,
    const __nv_bfloat16* __restrict__ Ahi, const __nv_bfloat16* __restrict__ Alo,
    const __nv_bfloat16* __restrict__ Bhi, const __nv_bfloat16* __restrict__ Blo,
    int m0, int n0, int lda, int ldb, int kk, int tid)
{
#pragma unroll
    for (int j = 0; j < 4; j++) {
        const int c = tid + j * 256;
        const int row = c >> 3;
        const int k8 = (c & 7) * 8;
        const size_t ga = (size_t)(m0 + row) * lda + kk + k8;
        const size_t gb = (size_t)(n0 + row) * ldb + kk + k8;
        const uint32_t so = SMEM_SWIZZLE_128B((uint32_t)(row * 128 + k8 * 2));
        CP_ASYNC16(sdst + so,         Ahi + ga);
        CP_ASYNC16(sdst + 16384 + so, Alo + ga);
        CP_ASYNC16(sdst + 32768 + so, Bhi + gb);
        CP_ASYNC16(sdst + 49152 + so, Blo + gb);
    }
}

template <int EPI>
__global__ void __launch_bounds__(256, 1)
mma_gemm(const __nv_bfloat16* __restrict__ Ahi, const __nv_bfloat16* __restrict__ Alo,
         const __nv_bfloat16* __restrict__ Bhi, const __nv_bfloat16* __restrict__ Blo,
         float* __restrict__ Cf, float* __restrict__ Cf2,
         __nv_bfloat16* __restrict__ Chi, __nv_bfloat16* __restrict__ Clo,
         const float* __restrict__ Zp,
         int K, int lda, int ldb, int ldc)
{
    extern __shared__ char smem[];
    const uint32_t sb = smem_to_u32(smem);
    const int tid  = threadIdx.x;
    const int lane = tid & 31;
    const int wid  = tid >> 5;
    const int wm   = wid & 1;     // 2 M-groups of 64 rows
    const int wn   = wid >> 1;    // 4 N-groups of 32 cols
    const int m0 = blockIdx.y * 128;
    const int n0 = blockIdx.x * 128;
    const int nk = K >> 6;

    if (EPI == 3) {
        const int b = blockIdx.z >> 3;
        const int h = blockIdx.z & 7;
        const size_t aoff = (size_t)b * 8192 * 1024 + (size_t)h * 128;
        Ahi += aoff; Alo += aoff;
        const size_t boff = (size_t)blockIdx.z * (128 * 128);
        Bhi += boff; Blo += boff;
        Chi += aoff; Clo += aoff;
        Zp  += (size_t)b * 8192 * 8 + h;
    }

    float acc[4][4][4];
#pragma unroll
    for (int i = 0; i < 4; i++)
#pragma unroll
        for (int j = 0; j < 4; j++)
#pragma unroll
            for (int p = 0; p < 4; p++) acc[i][j][p] = 0.f;

    // prologue: fill up to 3 stages
#pragma unroll
    for (int s = 0; s < 3; s++) {
        if (s < nk) mg_load_stage(sb + s * MG_STAGE, Ahi, Alo, Bhi, Blo,
                                  m0, n0, lda, ldb, s * 64, tid);
        CP_COMMIT();
    }

    const int a_row  = (lane & 15);
    const int a_colh = (lane >> 4) * 16;
    const int b_row  = ((lane >> 4) << 3) + (lane & 7);
    const int b_colh = ((lane >> 3) & 1) * 16;

    for (int kt = 0; kt < nk; kt++) {
        CP_WAIT2();
        __syncthreads();
        const uint32_t sa = sb + (kt % 3) * MG_STAGE;

#pragma unroll
        for (int ks = 0; ks < 4; ks++) {
            const int kb = ks * 32;
            uint32_t ah[4][4], al[4][4];
#pragma unroll
            for (int mt = 0; mt < 4; mt++) {
                const int row = wm * 64 + mt * 16 + a_row;
                const uint32_t off = SMEM_SWIZZLE_128B((uint32_t)(row * 128 + kb + a_colh));
                LDSM4(ah[mt][0], ah[mt][1], ah[mt][2], ah[mt][3], sa + off);
                LDSM4(al[mt][0], al[mt][1], al[mt][2], al[mt][3], sa + 16384 + off);
            }
            uint32_t bh[4][2], bl[4][2];
#pragma unroll
            for (int lg = 0; lg < 2; lg++) {
                const int row = wn * 32 + lg * 16 + b_row;
                const uint32_t off = SMEM_SWIZZLE_128B((uint32_t)(row * 128 + kb + b_colh));
                uint32_t r0, r1, r2, r3;
                LDSM4(r0, r1, r2, r3, sa + 32768 + off);
                bh[lg * 2][0] = r0; bh[lg * 2][1] = r1;
                bh[lg * 2 + 1][0] = r2; bh[lg * 2 + 1][1] = r3;
                LDSM4(r0, r1, r2, r3, sa + 49152 + off);
                bl[lg * 2][0] = r0; bl[lg * 2][1] = r1;
                bl[lg * 2 + 1][0] = r2; bl[lg * 2 + 1][1] = r3;
            }
#pragma unroll
            for (int mt = 0; mt < 4; mt++)
#pragma unroll
                for (int nf = 0; nf < 4; nf++) {
                    mma16816(acc[mt][nf], ah[mt], bh[nf][0], bh[nf][1]);
                    mma16816(acc[mt][nf], ah[mt], bl[nf][0], bl[nf][1]);
                    mma16816(acc[mt][nf], al[mt], bh[nf][0], bh[nf][1]);
                }
        }
        __syncthreads();
        if (kt + 3 < nk)
            mg_load_stage(sb + (kt % 3) * MG_STAGE, Ahi, Alo, Bhi, Blo,
                          m0, n0, lda, ldb, (kt + 3) * 64, tid);
        CP_COMMIT();
    }

    // -------- epilogue: acc -> gmem --------
#pragma unroll
    for (int mt = 0; mt < 4; mt++) {
#pragma unroll
        for (int nf = 0; nf < 4; nf++) {
            const int r0 = m0 + wm * 64 + mt * 16 + (lane >> 2);
            const int c0 = n0 + wn * 32 + nf * 8 + (lane & 3) * 2;
#pragma unroll
            for (int half = 0; half < 2; half++) {
                const int r = r0 + half * 8;
                float vx = acc[mt][nf][half * 2];
                float vy = acc[mt][nf][half * 2 + 1];
                const size_t o = (size_t)r * ldc + c0;
                if (EPI == 0) {
                    *(float2*)(Cf + o) = make_float2(vx, vy);
                } else if (EPI == 1) {
                    *(float2*)(Cf + o) = make_float2(vx, vy);
                    float fx = vx > 0.f ? vx + 1.f : expf(vx);
                    float fy = vy > 0.f ? vy + 1.f : expf(vy);
                    *(float2*)(Cf2 + o) = make_float2(fx, fy);
                    __nv_bfloat162 hh, ll;
                    split1(fx, hh.x, ll.x);
                    split1(fy, hh.y, ll.y);
                    *(__nv_bfloat162*)(Chi + o) = hh;
                    *(__nv_bfloat162*)(Clo + o) = ll;
                } else if (EPI == 2) {
                    vx = fmaxf(vx, 0.f);
                    vy = fmaxf(vy, 0.f);
                    __nv_bfloat162 hh, ll;
                    split1(vx, hh.x, ll.x);
                    split1(vy, hh.y, ll.y);
                    *(__nv_bfloat162*)(Chi + o) = hh;
                    *(__nv_bfloat162*)(Clo + o) = ll;
                } else if (EPI == 3) {
                    const float zs = Zp[(size_t)r * 8];
                    vx *= zs; vy *= zs;
                    __nv_bfloat162 hh, ll;
                    split1(vx, hh.x, ll.x);
                    split1(vy, hh.y, ll.y);
                    *(__nv_bfloat162*)(Chi + o) = hh;
                    *(__nv_bfloat162*)(Clo + o) = ll;
                } else { // EPI == 4
                    *(float2*)(Cf + o) = make_float2(vx, vy);
                    __nv_bfloat162 hh, ll;
                    split1(vx, hh.x, ll.x);
                    split1(vy, hh.y, ll.y);
                    *(__nv_bfloat162*)(Chi + o) = hh;
                    *(__nv_bfloat162*)(Clo + o) = ll;
                }
            }
        }
    }
}

// ===================== fp32 -> bf16 hi/lo split (vectorized) =================
__global__ void cvt_hilo(const float4* __restrict__ in, uint2* __restrict__ hi,
                         uint2* __restrict__ lo, int n4)
{
    int i = blockIdx.x * blockDim.x + threadIdx.x;
    if (i >= n4) return;
    float4 v = in[i];
    __nv_bfloat162 h01, h23, l01, l23;
    split1(v.x, h01.x, l01.x); split1(v.y, h01.y, l01.y);
    split1(v.z, h23.x, l23.x); split1(v.w, h23.y, l23.y);
    hi[i] = make_uint2(*reinterpret_cast<uint32_t*>(&h01), *reinterpret_cast<uint32_t*>(&h23));
    lo[i] = make_uint2(*reinterpret_cast<uint32_t*>(&l01), *reinterpret_cast<uint32_t*>(&l23));
}

// =============== weight transpose + split: W[K,N] -> WT hi/lo [N,K] ==========
__global__ void wtrans(const float* __restrict__ W, __nv_bfloat16* __restrict__ hi,
                       __nv_bfloat16* __restrict__ lo, int K, int N)
{
    __shared__ float t[32][33];
    const int n0 = blockIdx.x * 32, k0 = blockIdx.y * 32;
    const int tx = threadIdx.x, ty = threadIdx.y;
#pragma unroll
    for (int r = 0; r < 4; r++)
        t[ty + 8 * r][tx] = W[(size_t)(k0 + ty + 8 * r) * N + n0 + tx];
    __syncthreads();
#pragma unroll
    for (int r = 0; r < 4; r++) {
        float v = t[tx][ty + 8 * r];
        __nv_bfloat16 h, l;
        split1(v, h, l);
        const size_t o = (size_t)(n0 + ty + 8 * r) * K + k0 + tx;
        hi[o] = h; lo[o] = l;
    }
}

__global__ void zero_kernel(float* __restrict__ p, int n) {
    int i = blockIdx.x * blockDim.x + threadIdx.x;
    if (i < n) p[i] = 0.f;
}

// ------------- KV^T = sum_s V[s] (x) K[s]  and  Ksum = sum_s K[s] ------------
// double-buffered smem, register prefetch, ONE sync per 4-row stage.
// NOTE: writes the TRANSPOSE (KVt[v][d]) so it can feed mma_gemm's B operand
// ([N,K] K-major) directly.
__global__ void __launch_bounds__(256)
kv_kernel(const float* __restrict__ feat, const float* __restrict__ q,
          float* __restrict__ KV, float* __restrict__ Ksum)
{
    const int bh = blockIdx.y;
    const int b = bh >> 3, h = bh & 7;
    const float* Kp = feat + (size_t)b * 8192 * 1024 + (size_t)h * 128;
    const float* Vp = q    + (size_t)b * 8192 * 1024 + (size_t)h * 128;
    const int s0 = blockIdx.x * 256;

    __shared__ float Ks[2][4][128];
    __shared__ float Vs[2][4][128];

    const int tid = threadIdx.x;
    const int ty = tid >> 4, tx = tid & 15;
    const int lrow = (tid & 127) >> 5;
    const int lcol = ((tid & 127) & 31) << 2;
    const bool loadV = (tid >= 128);
    const float* src = loadV ? Vp : Kp;

    float acc[8][8];
#pragma unroll
    for (int i = 0; i < 8; i++)
#pragma unroll
        for (int j = 0; j < 8; j++) acc[i][j] = 0.f;
    float ksacc = 0.f;

    // prologue: stage 0
    {
        float4 v = *(const float4*)(src + (size_t)(s0 + lrow) * 1024 + lcol);
        float* dst = loadV ? &Vs[0][lrow][lcol] : &Ks[0][lrow][lcol];
        *(float4*)dst = v;
    }
    __syncthreads();

    int cur = 0;
    for (int it = 0; it < 64; it++) {
        float4 nv;
        const bool has = (it + 1 < 64);
        if (has)
            nv = *(const float4*)(src + (size_t)(s0 + (it + 1) * 4 + lrow) * 1024 + lcol);
#pragma unroll
        for (int ss = 0; ss < 4; ss++) {
            float av[8], bv[8];
            *(float4*)&av[0] = *(const float4*)&Ks[cur][ss][ty * 8];
            *(float4*)&av[4] = *(const float4*)&Ks[cur][ss][ty * 8 + 4];
            *(float4*)&bv[0] = *(const float4*)&Vs[cur][ss][tx * 8];
            *(float4*)&bv[4] = *(const float4*)&Vs[cur][ss][tx * 8 + 4];
#pragma unroll
            for (int i = 0; i < 8; i++)
#pragma unroll
                for (int j = 0; j < 8; j++)
                    acc[i][j] = fmaf(av[i], bv[j], acc[i][j]);
            if (tid < 128) ksacc += Ks[cur][ss][tid];
        }
        if (has) {
            const int nb = cur ^ 1;
            float* dst = loadV ? &Vs[nb][lrow][lcol] : &Ks[nb][lrow][lcol];
            *(float4*)dst = nv;
            __syncthreads();
            cur = nb;
        }
    }

    // acc[i][j] = sum K[d=ty*8+i] * V[v=tx*8+j]; store TRANSPOSED: KVt[v][d]
    float* KVp = KV + (size_t)bh * 128 * 128;
#pragma unroll
    for (int i = 0; i < 8; i++)
#pragma unroll
        for (int j = 0; j < 8; j++)
            atomicAdd(&KVp[(tx * 8 + j) * 128 + ty * 8 + i], acc[i][j]);
    if (tid < 128) atomicAdd(&Ksum[bh * 128 + tid], ksacc);
}

// ---------------- Z = 1 / (Q . Ksum + eps) -----------------------------------
__global__ void __launch_bounds__(256)
z_kernel(const float* __restrict__ feat, const float* __restrict__ Ksum,
         float* __restrict__ Z)
{
    const int wid  = (blockIdx.x * blockDim.x + threadIdx.x) >> 5;
    const int lane = threadIdx.x & 31;
    const int tok = wid >> 3;
    const int h = wid & 7;
    const int b = tok >> 13;
    float4 f  = *(const float4*)(feat + (size_t)tok * 1024 + h * 128 + lane * 4);
    float4 ks = *(const float4*)(Ksum + ((b * 8 + h) * 128) + lane * 4);
    float s = f.x * ks.x + f.y * ks.y + f.z * ks.z + f.w * ks.w;
#pragma unroll
    for (int o = 16; o; o >>= 1) s += __shfl_xor_sync(0xffffffffu, s, o);
    if (lane == 0) Z[wid] = 1.f / (s + 1e-6f);
}

// ---------------- out = xin + LayerNorm(y; g, beta) --------------------------
__global__ void __launch_bounds__(256)
ln_kernel(const float* __restrict__ y, const float* __restrict__ xin,
          const float* __restrict__ g, const float* __restrict__ beta,
          float* __restrict__ out)
{
    const int r = blockIdx.x;
    const int tid = threadIdx.x;
    const size_t base = (size_t)r * 1024 + tid * 4;
    float4 v = *(const float4*)(y + base);
    float s  = v.x + v.y + v.z + v.w;
    float sq = v.x * v.x + v.y * v.y + v.z * v.z + v.w * v.w;
#pragma unroll
    for (int o = 16; o; o >>= 1) {
        s  += __shfl_xor_sync(0xffffffffu, s, o);
        sq += __shfl_xor_sync(0xffffffffu, sq, o);
    }
    __shared__ float shs[8], shq[8];
    if ((tid & 31) == 0) { shs[tid >> 5] = s; shq[tid >> 5] = sq; }
    __syncthreads();
    float tot = 0.f, totq = 0.f;
#pragma unroll
    for (int w = 0; w < 8; w++) { tot += shs[w]; totq += shq[w]; }
    const float mu   = tot * (1.f / 1024.f);
    const float var  = totq * (1.f / 1024.f) - mu * mu;
    const float rstd = rsqrtf(var + 1e-5f);
    float4 gv = *(const float4*)(g + tid * 4);
    float4 bv = *(const float4*)(beta + tid * 4);
    float4 xv = *(const float4*)(xin + base);
    float4 o;
    o.x = xv.x + (v.x - mu) * rstd * gv.x + bv.x;
    o.y = xv.y + (v.y - mu) * rstd * gv.y + bv.y;
    o.z = xv.z + (v.z - mu) * rstd * gv.z + bv.z;
    o.w = xv.w + (v.w - mu) * rstd * gv.w + bv.w;
    *(float4*)(out + base) = o;
}

// -----------------------------------------------------------------------------
extern "C" void kernel_launch(void* const* d_in, const int* in_sizes, int n_in,
                              void* d_out, int out_size)
{
    const float* x  = (const float*)d_in[0];
    const float* Wq = (const float*)d_in[1];
    const float* Wm = (const float*)d_in[2];
    const float* W1 = (const float*)d_in[3];
    const float* W2 = (const float*)d_in[4];
    const float* g1 = (const float*)d_in[5];
    const float* b1 = (const float*)d_in[6];
    const float* g2 = (const float*)d_in[7];
    const float* b2 = (const float*)d_in[8];
    float* outp = (float*)d_out;

    float *qp, *featp, *KVp, *Ksump, *Zp, *msgWp, *x1p, *mlpp;
    cudaGetSymbolAddress((void**)&qp,    g_q);
    cudaGetSymbolAddress((void**)&featp, g_feat);
    cudaGetSymbolAddress((void**)&KVp,   g_KV);
    cudaGetSymbolAddress((void**)&Ksump, g_Ksum);
    cudaGetSymbolAddress((void**)&Zp,    g_Z);
    cudaGetSymbolAddress((void**)&msgWp, g_msgW);
    cudaGetSymbolAddress((void**)&x1p,   g_x1);
    cudaGetSymbolAddress((void**)&mlpp,  g_mlp);

    __nv_bfloat16 *xhi, *xlo, *fhi, *flo, *msghi, *msglo, *mwhi, *mwlo;
    __nv_bfloat16 *hidhi, *hidlo, *kvhi, *kvlo;
    __nv_bfloat16 *wqh, *wql, *wmh, *wml, *w1h, *w1l, *w2h, *w2l;
    cudaGetSymbolAddress((void**)&xhi,   g_xhi);
    cudaGetSymbolAddress((void**)&xlo,   g_xlo);
    cudaGetSymbolAddress((void**)&fhi,   g_fhi);
    cudaGetSymbolAddress((void**)&flo,   g_flo);
    cudaGetSymbolAddress((void**)&msghi, g_msghi);
    cudaGetSymbolAddress((void**)&msglo, g_msglo);
    cudaGetSymbolAddress((void**)&mwhi,  g_mwhi);
    cudaGetSymbolAddress((void**)&mwlo,  g_mwlo);
    cudaGetSymbolAddress((void**)&hidhi, g_hidhi);
    cudaGetSymbolAddress((void**)&hidlo, g_hidlo);
    cudaGetSymbolAddress((void**)&kvhi,  g_KVhi);
    cudaGetSymbolAddress((void**)&kvlo,  g_KVlo);
    cudaGetSymbolAddress((void**)&wqh,   g_wqt_h);
    cudaGetSymbolAddress((void**)&wql,   g_wqt_l);
    cudaGetSymbolAddress((void**)&wmh,   g_wmt_h);
    cudaGetSymbolAddress((void**)&wml,   g_wmt_l);
    cudaGetSymbolAddress((void**)&w1h,   g_w1t_h);
    cudaGetSymbolAddress((void**)&w1l,   g_w1t_l);
    cudaGetSymbolAddress((void**)&w2h,   g_w2t_h);
    cudaGetSymbolAddress((void**)&w2l,   g_w2t_l);

    cudaFuncSetAttribute(mma_gemm<0>, cudaFuncAttributeMaxDynamicSharedMemorySize, MG_SMEM);
    cudaFuncSetAttribute(mma_gemm<1>, cudaFuncAttributeMaxDynamicSharedMemorySize, MG_SMEM);
    cudaFuncSetAttribute(mma_gemm<2>, cudaFuncAttributeMaxDynamicSharedMemorySize, MG_SMEM);
    cudaFuncSetAttribute(mma_gemm<3>, cudaFuncAttributeMaxDynamicSharedMemorySize, MG_SMEM);
    cudaFuncSetAttribute(mma_gemm<4>, cudaFuncAttributeMaxDynamicSharedMemorySize, MG_SMEM);

    const dim3 blk(256);
    const dim3 tblk(32, 8);
    const int n4 = NTOK * DIM / 4;

    // ---- weight transpose + split; x split ----
    wtrans<<<dim3(32, 32), tblk>>>(Wq, wqh, wql, 1024, 1024);
    wtrans<<<dim3(32, 32), tblk>>>(Wm, wmh, wml, 1024, 1024);
    wtrans<<<dim3(64, 32), tblk>>>(W1, w1h, w1l, 1024, 2048);
    wtrans<<<dim3(32, 64), tblk>>>(W2, w2h, w2l, 2048, 1024);
    cvt_hilo<<<n4 / 256, blk>>>((const float4*)x, (uint2*)xhi, (uint2*)xlo, n4);

    // 1) q = x @ Wq ; feat = elu(q)+1 (fp32 + hi/lo)
    mma_gemm<1><<<dim3(8, 128), blk, MG_SMEM>>>(xhi, xlo, wqh, wql,
                                                qp, featp, fhi, flo, nullptr,
                                                1024, 1024, 1024, 1024);

    // 2) KV^T / Ksum
    zero_kernel<<<(16 * 128 * 128 + 255) / 256, blk>>>(KVp, 16 * 128 * 128);
    zero_kernel<<<(16 * 128 + 255) / 256, blk>>>(Ksump, 16 * 128);
    kv_kernel<<<dim3(32, 16), blk>>>(featp, qp, KVp, Ksump);

    // 3) Z normalizer
    z_kernel<<<16384, blk>>>(featp, Ksump, Zp);

    // 4) KV^T -> hi/lo ; msg = (feat @ KV) * Z -> msg hi/lo  (mma, batched)
    cvt_hilo<<<(16 * 128 * 128 / 4) / 256, blk>>>((const float4*)KVp,
                                                  (uint2*)kvhi, (uint2*)kvlo,
                                                  16 * 128 * 128 / 4);
    mma_gemm<3><<<dim3(1, 64, 16), blk, MG_SMEM>>>(fhi, flo, kvhi, kvlo,
                                                   nullptr, nullptr, msghi, msglo, Zp,
                                                   128, 1024, 128, 1024);

    // 5) msgW = msg @ Wm  (fp32 + hi/lo)
    mma_gemm<4><<<dim3(8, 128), blk, MG_SMEM>>>(msghi, msglo, wmh, wml,
                                                msgWp, nullptr, mwhi, mwlo, nullptr,
                                                1024, 1024, 1024, 1024);

    // 6) x1 = x + LN(msgW)
    ln_kernel<<<16384, blk>>>(msgWp, x, g1, b1, x1p);

    // 7) hid = relu(msgW @ W1) -> hi/lo
    mma_gemm<2><<<dim3(16, 128), blk, MG_SMEM>>>(mwhi, mwlo, w1h, w1l,
                                                 nullptr, nullptr, hidhi, hidlo, nullptr,
                                                 1024, 1024, 1024, 2048);

    // 8) mlp = hid @ W2  (K=2048)
    mma_gemm<0><<<dim3(8, 128), blk, MG_SMEM>>>(hidhi, hidlo, w2h, w2l,
                                                mlpp, nullptr, nullptr, nullptr, nullptr,
                                                2048, 2048, 2048, 1024);

    // 9) out = x1 + LN(mlp)
    ln_kernel<<<16384, blk>>>(mlpp, x1p, g2, b2, outp);
}

// round 16
// speedup vs baseline: 3.0012x; 1.1751x over previous
#include <cuda_runtime.h>
#include <cuda_bf16.h>
#include <cuda_fp16.h>
#include <math.h>
#include <stdint.h>

// Problem constants: B=2, L=8192, D=1024, H=8, d=128
#define NTOK 16384            // B*L
#define DIM  1024
#define NH   8
#define HD   128

// ---------------- scratch (device globals; no allocs allowed) ----------------
__device__ float g_q   [(size_t)NTOK * DIM];
__device__ float g_feat[(size_t)NTOK * DIM];
__device__ float g_KV  [16 * HD * HD];    // holds KV^T per (b,h): [v][d]
__device__ float g_Ksum[16 * HD];
__device__ float g_Z   [(size_t)NTOK * NH];
__device__ float g_msgW[(size_t)NTOK * DIM];
__device__ float g_x1  [(size_t)NTOK * DIM];
__device__ float g_mlp [(size_t)NTOK * DIM];

// split operands (2-byte elements; bf16 or fp16 per consumer)
__device__ __nv_bfloat16 g_xhi  [(size_t)NTOK * DIM];
__device__ __nv_bfloat16 g_xlo  [(size_t)NTOK * DIM];
__device__ __nv_bfloat16 g_fhi  [(size_t)NTOK * DIM];   // feat hi (bf16)
__device__ __nv_bfloat16 g_flo  [(size_t)NTOK * DIM];   // feat lo (bf16)
__device__ __nv_bfloat16 g_msghi[(size_t)NTOK * DIM];   // msg hi (bf16)
__device__ __nv_bfloat16 g_msglo[(size_t)NTOK * DIM];
__device__ __half        g_mwhi [(size_t)NTOK * DIM];   // msgW hi (fp16)
__device__ __half        g_mwlo [(size_t)NTOK * DIM];
__device__ __half        g_hidhi[(size_t)NTOK * 2 * DIM]; // hid hi (fp16)
__device__ __half        g_hidlo[(size_t)NTOK * 2 * DIM];
__device__ __nv_bfloat16 g_KVhi [16 * HD * HD];
__device__ __nv_bfloat16 g_KVlo [16 * HD * HD];
__device__ __nv_bfloat16 g_wqt_h[DIM * DIM];
__device__ __nv_bfloat16 g_wqt_l[DIM * DIM];
__device__ __nv_bfloat16 g_wmt_h[DIM * DIM];
__device__ __nv_bfloat16 g_wmt_l[DIM * DIM];
__device__ __half        g_w1t_h[2 * DIM * DIM];        // W1^T hi (fp16 only)
__device__ __half        g_w2t_h[2 * DIM * DIM];        // W2^T hi (fp16 only)

// =========================== helpers =========================================
__device__ __forceinline__ uint32_t smem_to_u32(const void* p) {
    uint32_t a;
    asm("{ .reg .u64 t; cvta.to.shared.u64 t, %1; cvt.u32.u64 %0, t; }"
        : "=r"(a) : "l"(p));
    return a;
}

#define SMEM_SWIZZLE_128B(o) ((o) ^ (((o) >> 3) & 0x70))

#define CP_ASYNC16(smem_u32, gptr) \
    asm volatile("cp.async.cg.shared.global [%0], [%1], 16;" \
        :: "r"(smem_u32), "l"(gptr))
#define CP_COMMIT() asm volatile("cp.async.commit_group;" ::: "memory")
#define CP_WAIT2()  asm volatile("cp.async.wait_group 2;" ::: "memory")

#define LDSM4(r0, r1, r2, r3, addr) \
    asm volatile("ldmatrix.sync.aligned.m8n8.x4.shared.b16 {%0,%1,%2,%3}, [%4];" \
        : "=r"(r0), "=r"(r1), "=r"(r2), "=r"(r3) : "r"(addr))

__device__ __forceinline__ void mma16816_bf16(float* c, const uint32_t* a,
                                              uint32_t b0, uint32_t b1) {
    asm volatile(
        "mma.sync.aligned.m16n8k16.row.col.f32.bf16.bf16.f32 "
        "{%0,%1,%2,%3}, {%4,%5,%6,%7}, {%8,%9}, {%0,%1,%2,%3};"
        : "+f"(c[0]), "+f"(c[1]), "+f"(c[2]), "+f"(c[3])
        : "r"(a[0]), "r"(a[1]), "r"(a[2]), "r"(a[3]), "r"(b0), "r"(b1));
}
__device__ __forceinline__ void mma16816_f16(float* c, const uint32_t* a,
                                             uint32_t b0, uint32_t b1) {
    asm volatile(
        "mma.sync.aligned.m16n8k16.row.col.f32.f16.f16.f32 "
        "{%0,%1,%2,%3}, {%4,%5,%6,%7}, {%8,%9}, {%0,%1,%2,%3};"
        : "+f"(c[0]), "+f"(c[1]), "+f"(c[2]), "+f"(c[3])
        : "r"(a[0]), "r"(a[1]), "r"(a[2]), "r"(a[3]), "r"(b0), "r"(b1));
}

__device__ __forceinline__ void split1(float a, __nv_bfloat16& h, __nv_bfloat16& l) {
    h = __float2bfloat16_rn(a);
    l = __float2bfloat16_rn(a - __bfloat162float(h));
}
__device__ __forceinline__ void split1h(float a, __half& h, __half& l) {
    h = __float2half_rn(a);
    l = __float2half_rn(a - __half2float(h));
}

// PROD==3: 4 tiles/stage (Ahi,Alo,Bhi,Blo) = 64KB; PROD==2: 3 tiles = 48KB
static constexpr int MG_SMEM3 = 3 * 65536;   // 196608
static constexpr int MG_SMEM2 = 3 * 49152;   // 147456

// =============== mma.sync split GEMM: C[M,N] = A[M,K] @ B^T ==================
// A: [M,K] rows stride lda (hi/lo, 2-byte).  B: [N,K] rows stride ldb (W^T).
// PROD==3 (bf16): AhiBhi + AhiBlo + AloBhi.  PROD==2 (fp16): AhiBhi + AloBhi.
// EPI 0: store Cf fp32.
// EPI 1: store Cf=q fp32, Cf2=feat fp32, Chi/Clo = feat hi/lo bf16.
// EPI 2: relu, store Chi/Clo fp16 split.
// EPI 3: batched over blockIdx.z=bh; scale by Z; Chi/Clo = msg hi/lo bf16.
// EPI 4: store Cf fp32 AND Chi/Clo fp16 split.
template <int PROD>
__device__ __forceinline__ void mg_load_stage(
    uint32_t sdst,
    const void* __restrict__ Ahi, const void* __restrict__ Alo,
    const void* __restrict__ Bhi, const void* __restrict__ Blo,
    int m0, int n0, int lda, int ldb, int kk, int tid)
{
#pragma unroll
    for (int j = 0; j < 4; j++) {
        const int c = tid + j * 256;
        const int row = c >> 3;
        const int k8 = (c & 7) * 8;
        const size_t ga = (size_t)(m0 + row) * lda + kk + k8;
        const size_t gb = (size_t)(n0 + row) * ldb + kk + k8;
        const uint32_t so = SMEM_SWIZZLE_128B((uint32_t)(row * 128 + k8 * 2));
        CP_ASYNC16(sdst + so,         (const uint16_t*)Ahi + ga);
        CP_ASYNC16(sdst + 16384 + so, (const uint16_t*)Alo + ga);
        CP_ASYNC16(sdst + 32768 + so, (const uint16_t*)Bhi + gb);
        if (PROD == 3)
            CP_ASYNC16(sdst + 49152 + so, (const uint16_t*)Blo + gb);
    }
}

template <int EPI, int PROD>
__global__ void __launch_bounds__(256, 1)
mma_gemm(const void* __restrict__ Ahi, const void* __restrict__ Alo,
         const void* __restrict__ Bhi, const void* __restrict__ Blo,
         float* __restrict__ Cf, float* __restrict__ Cf2,
         void* __restrict__ Chi, void* __restrict__ Clo,
         const float* __restrict__ Zp,
         int K, int lda, int ldb, int ldc)
{
    extern __shared__ char smem[];
    constexpr int STAGE = (PROD == 3) ? 65536 : 49152;
    const uint32_t sb = smem_to_u32(smem);
    const int tid  = threadIdx.x;
    const int lane = tid & 31;
    const int wid  = tid >> 5;
    const int wm   = wid & 1;     // 2 M-groups of 64 rows
    const int wn   = wid >> 1;    // 4 N-groups of 32 cols
    const int m0 = blockIdx.y * 128;
    const int n0 = blockIdx.x * 128;
    const int nk = K >> 6;

    size_t coff = 0;
    if (EPI == 3) {
        const int b = blockIdx.z >> 3;
        const int h = blockIdx.z & 7;
        const size_t aoff = (size_t)b * 8192 * 1024 + (size_t)h * 128;
        Ahi = (const uint16_t*)Ahi + aoff;
        Alo = (const uint16_t*)Alo + aoff;
        const size_t boff = (size_t)blockIdx.z * (128 * 128);
        Bhi = (const uint16_t*)Bhi + boff;
        Blo = (const uint16_t*)Blo + boff;
        coff = aoff;
        Zp  += (size_t)b * 8192 * 8 + h;
    }

    float acc[4][4][4];
#pragma unroll
    for (int i = 0; i < 4; i++)
#pragma unroll
        for (int j = 0; j < 4; j++)
#pragma unroll
            for (int p = 0; p < 4; p++) acc[i][j][p] = 0.f;

    // prologue: fill up to 3 stages
#pragma unroll
    for (int s = 0; s < 3; s++) {
        if (s < nk) mg_load_stage<PROD>(sb + s * STAGE, Ahi, Alo, Bhi, Blo,
                                        m0, n0, lda, ldb, s * 64, tid);
        CP_COMMIT();
    }

    const int a_row  = (lane & 15);
    const int a_colh = (lane >> 4) * 16;
    const int b_row  = ((lane >> 4) << 3) + (lane & 7);
    const int b_colh = ((lane >> 3) & 1) * 16;

    for (int kt = 0; kt < nk; kt++) {
        CP_WAIT2();
        __syncthreads();
        const uint32_t sa = sb + (kt % 3) * STAGE;

#pragma unroll
        for (int ks = 0; ks < 4; ks++) {
            const int kb = ks * 32;
            uint32_t ah[4][4], al[4][4];
#pragma unroll
            for (int mt = 0; mt < 4; mt++) {
                const int row = wm * 64 + mt * 16 + a_row;
                const uint32_t off = SMEM_SWIZZLE_128B((uint32_t)(row * 128 + kb + a_colh));
                LDSM4(ah[mt][0], ah[mt][1], ah[mt][2], ah[mt][3], sa + off);
                LDSM4(al[mt][0], al[mt][1], al[mt][2], al[mt][3], sa + 16384 + off);
            }
            uint32_t bh[4][2], bl[4][2];
#pragma unroll
            for (int lg = 0; lg < 2; lg++) {
                const int row = wn * 32 + lg * 16 + b_row;
                const uint32_t off = SMEM_SWIZZLE_128B((uint32_t)(row * 128 + kb + b_colh));
                uint32_t r0, r1, r2, r3;
                LDSM4(r0, r1, r2, r3, sa + 32768 + off);
                bh[lg * 2][0] = r0; bh[lg * 2][1] = r1;
                bh[lg * 2 + 1][0] = r2; bh[lg * 2 + 1][1] = r3;
                if constexpr (PROD == 3) {
                    LDSM4(r0, r1, r2, r3, sa + 49152 + off);
                    bl[lg * 2][0] = r0; bl[lg * 2][1] = r1;
                    bl[lg * 2 + 1][0] = r2; bl[lg * 2 + 1][1] = r3;
                }
            }
#pragma unroll
            for (int mt = 0; mt < 4; mt++)
#pragma unroll
                for (int nf = 0; nf < 4; nf++) {
                    if constexpr (PROD == 3) {
                        mma16816_bf16(acc[mt][nf], ah[mt], bh[nf][0], bh[nf][1]);
                        mma16816_bf16(acc[mt][nf], ah[mt], bl[nf][0], bl[nf][1]);
                        mma16816_bf16(acc[mt][nf], al[mt], bh[nf][0], bh[nf][1]);
                    } else {
                        mma16816_f16(acc[mt][nf], ah[mt], bh[nf][0], bh[nf][1]);
                        mma16816_f16(acc[mt][nf], al[mt], bh[nf][0], bh[nf][1]);
                    }
                }
        }
        __syncthreads();
        if (kt + 3 < nk)
            mg_load_stage<PROD>(sb + (kt % 3) * STAGE, Ahi, Alo, Bhi, Blo,
                                m0, n0, lda, ldb, (kt + 3) * 64, tid);
        CP_COMMIT();
    }

    // -------- epilogue: acc -> gmem --------
#pragma unroll
    for (int mt = 0; mt < 4; mt++) {
#pragma unroll
        for (int nf = 0; nf < 4; nf++) {
            const int r0 = m0 + wm * 64 + mt * 16 + (lane >> 2);
            const int c0 = n0 + wn * 32 + nf * 8 + (lane & 3) * 2;
#pragma unroll
            for (int half = 0; half < 2; half++) {
                const int r = r0 + half * 8;
                float vx = acc[mt][nf][half * 2];
                float vy = acc[mt][nf][half * 2 + 1];
                const size_t o = (size_t)r * ldc + c0 + coff;
                if (EPI == 0) {
                    *(float2*)(Cf + o) = make_float2(vx, vy);
                } else if (EPI == 1) {
                    *(float2*)(Cf + o) = make_float2(vx, vy);
                    float fx = vx > 0.f ? vx + 1.f : expf(vx);
                    float fy = vy > 0.f ? vy + 1.f : expf(vy);
                    *(float2*)(Cf2 + o) = make_float2(fx, fy);
                    __nv_bfloat162 hh, ll;
                    split1(fx, hh.x, ll.x);
                    split1(fy, hh.y, ll.y);
                    *(__nv_bfloat162*)((__nv_bfloat16*)Chi + o) = hh;
                    *(__nv_bfloat162*)((__nv_bfloat16*)Clo + o) = ll;
                } else if (EPI == 2) {
                    vx = fmaxf(vx, 0.f);
                    vy = fmaxf(vy, 0.f);
                    __half2 hh, ll;
                    split1h(vx, hh.x, ll.x);
                    split1h(vy, hh.y, ll.y);
                    *(__half2*)((__half*)Chi + o) = hh;
                    *(__half2*)((__half*)Clo + o) = ll;
                } else if (EPI == 3) {
                    const float zs = Zp[(size_t)r * 8];
                    vx *= zs; vy *= zs;
                    __nv_bfloat162 hh, ll;
                    split1(vx, hh.x, ll.x);
                    split1(vy, hh.y, ll.y);
                    *(__nv_bfloat162*)((__nv_bfloat16*)Chi + o) = hh;
                    *(__nv_bfloat162*)((__nv_bfloat16*)Clo + o) = ll;
                } else { // EPI == 4: fp32 + fp16 split
                    *(float2*)(Cf + o) = make_float2(vx, vy);
                    __half2 hh, ll;
                    split1h(vx, hh.x, ll.x);
                    split1h(vy, hh.y, ll.y);
                    *(__half2*)((__half*)Chi + o) = hh;
                    *(__half2*)((__half*)Clo + o) = ll;
                }
            }
        }
    }
}

// ===================== fp32 -> bf16 hi/lo split (vectorized) =================
__global__ void cvt_hilo(const float4* __restrict__ in, uint2* __restrict__ hi,
                         uint2* __restrict__ lo, int n4)
{
    int i = blockIdx.x * blockDim.x + threadIdx.x;
    if (i >= n4) return;
    float4 v = in[i];
    __nv_bfloat162 h01, h23, l01, l23;
    split1(v.x, h01.x, l01.x); split1(v.y, h01.y, l01.y);
    split1(v.z, h23.x, l23.x); split1(v.w, h23.y, l23.y);
    hi[i] = make_uint2(*reinterpret_cast<uint32_t*>(&h01), *reinterpret_cast<uint32_t*>(&h23));
    lo[i] = make_uint2(*reinterpret_cast<uint32_t*>(&l01), *reinterpret_cast<uint32_t*>(&l23));
}

// ======= weight transpose + split (bf16 hi/lo): W[K,N] -> WT [N,K] ===========
__global__ void wtrans(const float* __restrict__ W, __nv_bfloat16* __restrict__ hi,
                       __nv_bfloat16* __restrict__ lo, int K, int N)
{
    __shared__ float t[32][33];
    const int n0 = blockIdx.x * 32, k0 = blockIdx.y * 32;
    const int tx = threadIdx.x, ty = threadIdx.y;
#pragma unroll
    for (int r = 0; r < 4; r++)
        t[ty + 8 * r][tx] = W[(size_t)(k0 + ty + 8 * r) * N + n0 + tx];
    __syncthreads();
#pragma unroll
    for (int r = 0; r < 4; r++) {
        float v = t[tx][ty + 8 * r];
        __nv_bfloat16 h, l;
        split1(v, h, l);
        const size_t o = (size_t)(n0 + ty + 8 * r) * K + k0 + tx;
        hi[o] = h; lo[o] = l;
    }
}

// ======= weight transpose fp16 hi only: W[K,N] -> WT [N,K] ===================
__global__ void wtrans_h(const float* __restrict__ W, __half* __restrict__ hi,
                         int K, int N)
{
    __shared__ float t[32][33];
    const int n0 = blockIdx.x * 32, k0 = blockIdx.y * 32;
    const int tx = threadIdx.x, ty = threadIdx.y;
#pragma unroll
    for (int r = 0; r < 4; r++)
        t[ty + 8 * r][tx] = W[(size_t)(k0 + ty + 8 * r) * N + n0 + tx];
    __syncthreads();
#pragma unroll
    for (int r = 0; r < 4; r++) {
        const size_t o = (size_t)(n0 + ty + 8 * r) * K + k0 + tx;
        hi[o] = __float2half_rn(t[tx][ty + 8 * r]);
    }
}

__global__ void zero_kernel(float* __restrict__ p, int n) {
    int i = blockIdx.x * blockDim.x + threadIdx.x;
    if (i < n) p[i] = 0.f;
}

// ------------- KV^T = sum_s V[s] (x) K[s]  and  Ksum = sum_s K[s] ------------
// double-buffered smem, register prefetch, ONE sync per 4-row stage.
// Writes the TRANSPOSE (KVt[v][d]) to feed mma_gemm's B operand directly.
__global__ void __launch_bounds__(256)
kv_kernel(const float* __restrict__ feat, const float* __restrict__ q,
          float* __restrict__ KV, float* __restrict__ Ksum)
{
    const int bh = blockIdx.y;
    const int b = bh >> 3, h = bh & 7;
    const float* Kp = feat + (size_t)b * 8192 * 1024 + (size_t)h * 128;
    const float* Vp = q    + (size_t)b * 8192 * 1024 + (size_t)h * 128;
    const int s0 = blockIdx.x * 256;

    __shared__ float Ks[2][4][128];
    __shared__ float Vs[2][4][128];

    const int tid = threadIdx.x;
    const int ty = tid >> 4, tx = tid & 15;
    const int lrow = (tid & 127) >> 5;
    const int lcol = ((tid & 127) & 31) << 2;
    const bool loadV = (tid >= 128);
    const float* src = loadV ? Vp : Kp;

    float acc[8][8];
#pragma unroll
    for (int i = 0; i < 8; i++)
#pragma unroll
        for (int j = 0; j < 8; j++) acc[i][j] = 0.f;
    float ksacc = 0.f;

    {
        float4 v = *(const float4*)(src + (size_t)(s0 + lrow) * 1024 + lcol);
        float* dst = loadV ? &Vs[0][lrow][lcol] : &Ks[0][lrow][lcol];
        *(float4*)dst = v;
    }
    __syncthreads();

    int cur = 0;
    for (int it = 0; it < 64; it++) {
        float4 nv;
        const bool has = (it + 1 < 64);
        if (has)
            nv = *(const float4*)(src + (size_t)(s0 + (it + 1) * 4 + lrow) * 1024 + lcol);
#pragma unroll
        for (int ss = 0; ss < 4; ss++) {
            float av[8], bv[8];
            *(float4*)&av[0] = *(const float4*)&Ks[cur][ss][ty * 8];
            *(float4*)&av[4] = *(const float4*)&Ks[cur][ss][ty * 8 + 4];
            *(float4*)&bv[0] = *(const float4*)&Vs[cur][ss][tx * 8];
            *(float4*)&bv[4] = *(const float4*)&Vs[cur][ss][tx * 8 + 4];
#pragma unroll
            for (int i = 0; i < 8; i++)
#pragma unroll
                for (int j = 0; j < 8; j++)
                    acc[i][j] = fmaf(av[i], bv[j], acc[i][j]);
            if (tid < 128) ksacc += Ks[cur][ss][tid];
        }
        if (has) {
            const int nb = cur ^ 1;
            float* dst = loadV ? &Vs[nb][lrow][lcol] : &Ks[nb][lrow][lcol];
            *(float4*)dst = nv;
            __syncthreads();
            cur = nb;
        }
    }

    float* KVp = KV + (size_t)bh * 128 * 128;
#pragma unroll
    for (int i = 0; i < 8; i++)
#pragma unroll
        for (int j = 0; j < 8; j++)
            atomicAdd(&KVp[(tx * 8 + j) * 128 + ty * 8 + i], acc[i][j]);
    if (tid < 128) atomicAdd(&Ksum[bh * 128 + tid], ksacc);
}

// ---------------- Z = 1 / (Q . Ksum + eps) -----------------------------------
__global__ void __launch_bounds__(256)
z_kernel(const float* __restrict__ feat, const float* __restrict__ Ksum,
         float* __restrict__ Z)
{
    const int wid  = (blockIdx.x * blockDim.x + threadIdx.x) >> 5;
    const int lane = threadIdx.x & 31;
    const int tok = wid >> 3;
    const int h = wid & 7;
    const int b = tok >> 13;
    float4 f  = *(const float4*)(feat + (size_t)tok * 1024 + h * 128 + lane * 4);
    float4 ks = *(const float4*)(Ksum + ((b * 8 + h) * 128) + lane * 4);
    float s = f.x * ks.x + f.y * ks.y + f.z * ks.z + f.w * ks.w;
#pragma unroll
    for (int o = 16; o; o >>= 1) s += __shfl_xor_sync(0xffffffffu, s, o);
    if (lane == 0) Z[wid] = 1.f / (s + 1e-6f);
}

// ---------------- out = xin + LayerNorm(y; g, beta) --------------------------
__global__ void __launch_bounds__(256)
ln_kernel(const float* __restrict__ y, const float* __restrict__ xin,
          const float* __restrict__ g, const float* __restrict__ beta,
          float* __restrict__ out)
{
    const int r = blockIdx.x;
    const int tid = threadIdx.x;
    const size_t base = (size_t)r * 1024 + tid * 4;
    float4 v = *(const float4*)(y + base);
    float s  = v.x + v.y + v.z + v.w;
    float sq = v.x * v.x + v.y * v.y + v.z * v.z + v.w * v.w;
#pragma unroll
    for (int o = 16; o; o >>= 1) {
        s  += __shfl_xor_sync(0xffffffffu, s, o);
        sq += __shfl_xor_sync(0xffffffffu, sq, o);
    }
    __shared__ float shs[8], shq[8];
    if ((tid & 31) == 0) { shs[tid >> 5] = s; shq[tid >> 5] = sq; }
    __syncthreads();
    float tot = 0.f, totq = 0.f;
#pragma unroll
    for (int w = 0; w < 8; w++) { tot += shs[w]; totq += shq[w]; }
    const float mu   = tot * (1.f / 1024.f);
    const float var  = totq * (1.f / 1024.f) - mu * mu;
    const float rstd = rsqrtf(var + 1e-5f);
    float4 gv = *(const float4*)(g + tid * 4);
    float4 bv = *(const float4*)(beta + tid * 4);
    float4 xv = *(const float4*)(xin + base);
    float4 o;
    o.x = xv.x + (v.x - mu) * rstd * gv.x + bv.x;
    o.y = xv.y + (v.y - mu) * rstd * gv.y + bv.y;
    o.z = xv.z + (v.z - mu) * rstd * gv.z + bv.z;
    o.w = xv.w + (v.w - mu) * rstd * gv.w + bv.w;
    *(float4*)(out + base) = o;
}

// -----------------------------------------------------------------------------
extern "C" void kernel_launch(void* const* d_in, const int* in_sizes, int n_in,
                              void* d_out, int out_size)
{
    const float* x  = (const float*)d_in[0];
    const float* Wq = (const float*)d_in[1];
    const float* Wm = (const float*)d_in[2];
    const float* W1 = (const float*)d_in[3];
    const float* W2 = (const float*)d_in[4];
    const float* g1 = (const float*)d_in[5];
    const float* b1 = (const float*)d_in[6];
    const float* g2 = (const float*)d_in[7];
    const float* b2 = (const float*)d_in[8];
    float* outp = (float*)d_out;

    float *qp, *featp, *KVp, *Ksump, *Zp, *msgWp, *x1p, *mlpp;
    cudaGetSymbolAddress((void**)&qp,    g_q);
    cudaGetSymbolAddress((void**)&featp, g_feat);
    cudaGetSymbolAddress((void**)&KVp,   g_KV);
    cudaGetSymbolAddress((void**)&Ksump, g_Ksum);
    cudaGetSymbolAddress((void**)&Zp,    g_Z);
    cudaGetSymbolAddress((void**)&msgWp, g_msgW);
    cudaGetSymbolAddress((void**)&x1p,   g_x1);
    cudaGetSymbolAddress((void**)&mlpp,  g_mlp);

    __nv_bfloat16 *xhi, *xlo, *fhi, *flo, *msghi, *msglo, *kvhi, *kvlo;
    __half *mwhi, *mwlo, *hidhi, *hidlo, *w1h, *w2h;
    __nv_bfloat16 *wqh, *wql, *wmh, *wml;
    cudaGetSymbolAddress((void**)&xhi,   g_xhi);
    cudaGetSymbolAddress((void**)&xlo,   g_xlo);
    cudaGetSymbolAddress((void**)&fhi,   g_fhi);
    cudaGetSymbolAddress((void**)&flo,   g_flo);
    cudaGetSymbolAddress((void**)&msghi, g_msghi);
    cudaGetSymbolAddress((void**)&msglo, g_msglo);
    cudaGetSymbolAddress((void**)&mwhi,  g_mwhi);
    cudaGetSymbolAddress((void**)&mwlo,  g_mwlo);
    cudaGetSymbolAddress((void**)&hidhi, g_hidhi);
    cudaGetSymbolAddress((void**)&hidlo, g_hidlo);
    cudaGetSymbolAddress((void**)&kvhi,  g_KVhi);
    cudaGetSymbolAddress((void**)&kvlo,  g_KVlo);
    cudaGetSymbolAddress((void**)&wqh,   g_wqt_h);
    cudaGetSymbolAddress((void**)&wql,   g_wqt_l);
    cudaGetSymbolAddress((void**)&wmh,   g_wmt_h);
    cudaGetSymbolAddress((void**)&wml,   g_wmt_l);
    cudaGetSymbolAddress((void**)&w1h,   g_w1t_h);
    cudaGetSymbolAddress((void**)&w2h,   g_w2t_h);

    cudaFuncSetAttribute(mma_gemm<1,3>, cudaFuncAttributeMaxDynamicSharedMemorySize, MG_SMEM3);
    cudaFuncSetAttribute(mma_gemm<3,3>, cudaFuncAttributeMaxDynamicSharedMemorySize, MG_SMEM3);
    cudaFuncSetAttribute(mma_gemm<4,3>, cudaFuncAttributeMaxDynamicSharedMemorySize, MG_SMEM3);
    cudaFuncSetAttribute(mma_gemm<2,2>, cudaFuncAttributeMaxDynamicSharedMemorySize, MG_SMEM2);
    cudaFuncSetAttribute(mma_gemm<0,2>, cudaFuncAttributeMaxDynamicSharedMemorySize, MG_SMEM2);

    const dim3 blk(256);
    const dim3 tblk(32, 8);
    const int n4 = NTOK * DIM / 4;

    // ---- weight transpose + split; x split ----
    wtrans<<<dim3(32, 32), tblk>>>(Wq, wqh, wql, 1024, 1024);
    wtrans<<<dim3(32, 32), tblk>>>(Wm, wmh, wml, 1024, 1024);
    wtrans_h<<<dim3(64, 32), tblk>>>(W1, w1h, 1024, 2048);
    wtrans_h<<<dim3(32, 64), tblk>>>(W2, w2h, 2048, 1024);
    cvt_hilo<<<n4 / 256, blk>>>((const float4*)x, (uint2*)xhi, (uint2*)xlo, n4);

    // 1) q = x @ Wq ; feat = elu(q)+1 (fp32 + bf16 hi/lo)
    mma_gemm<1,3><<<dim3(8, 128), blk, MG_SMEM3>>>(xhi, xlo, wqh, wql,
                                                   qp, featp, fhi, flo, nullptr,
                                                   1024, 1024, 1024, 1024);

    // 2) KV^T / Ksum
    zero_kernel<<<(16 * 128 * 128 + 255) / 256, blk>>>(KVp, 16 * 128 * 128);
    zero_kernel<<<(16 * 128 + 255) / 256, blk>>>(Ksump, 16 * 128);
    kv_kernel<<<dim3(32, 16), blk>>>(featp, qp, KVp, Ksump);

    // 3) Z normalizer
    z_kernel<<<16384, blk>>>(featp, Ksump, Zp);

    // 4) KV^T -> hi/lo ; msg = (feat @ KV) * Z -> msg bf16 hi/lo (mma, batched)
    cvt_hilo<<<(16 * 128 * 128 / 4) / 256, blk>>>((const float4*)KVp,
                                                  (uint2*)kvhi, (uint2*)kvlo,
                                                  16 * 128 * 128 / 4);
    mma_gemm<3,3><<<dim3(1, 64, 16), blk, MG_SMEM3>>>(fhi, flo, kvhi, kvlo,
                                                      nullptr, nullptr, msghi, msglo, Zp,
                                                      128, 1024, 128, 1024);

    // 5) msgW = msg @ Wm  (fp32 + fp16 hi/lo out)
    mma_gemm<4,3><<<dim3(8, 128), blk, MG_SMEM3>>>(msghi, msglo, wmh, wml,
                                                   msgWp, nullptr, mwhi, mwlo, nullptr,
                                                   1024, 1024, 1024, 1024);

    // 6) x1 = x + LN(msgW)
    ln_kernel<<<16384, blk>>>(msgWp, x, g1, b1, x1p);

    // 7) hid = relu(msgW @ W1) -> fp16 hi/lo   (fp16 2-MMA)
    mma_gemm<2,2><<<dim3(16, 128), blk, MG_SMEM2>>>(mwhi, mwlo, w1h, nullptr,
                                                    nullptr, nullptr, hidhi, hidlo, nullptr,
                                                    1024, 1024, 1024, 2048);

    // 8) mlp = hid @ W2  (fp16 2-MMA, K=2048)
    mma_gemm<0,2><<<dim3(8, 128), blk, MG_SMEM2>>>(hidhi, hidlo, w2h, nullptr,
                                                   mlpp, nullptr, nullptr, nullptr, nullptr,
                                                   2048, 2048, 2048, 1024);

    // 9) out = x1 + LN(mlp)
    ln_kernel<<<16384, blk>>>(mlpp, x1p, g2, b2, outp);
}